// round 1
// baseline (speedup 1.0000x reference)
#include <cuda_runtime.h>
#include <math.h>

#define CC 128
#define TM 64
#define NMAX 300000
#define NWORDS (1u<<20)
#define STRIDE_Bc 4194304
#define STRIDE_Tc 262144
#define STRIDE_Hc 512

// ---------------- scratch (device globals; no allocation allowed) ----------------
__device__ float    g_X1[(size_t)NMAX*CC];
__device__ float    g_X2[(size_t)NMAX*CC];
__device__ unsigned g_bitmap[NWORDS];
__device__ unsigned g_wordscan[NWORDS];
__device__ unsigned g_blocksum[1024];
__device__ unsigned g_blockoff[1024];
__device__ unsigned g_U;
__device__ float    g_colsum[CC];
__device__ float    g_scale[CC];

// ---------------- zero per-iteration state ----------------
__global__ void zero_kernel() {
    unsigned i = blockIdx.x * blockDim.x + threadIdx.x;
    unsigned stride = gridDim.x * blockDim.x;
    for (unsigned w = i; w < NWORDS; w += stride) g_bitmap[w] = 0u;
    if (i < CC) g_colsum[i] = 0.f;
}

// ---------------- fused GEMM (C=128) + LayerNorm (+ReLU) (+column sums) ----------------
// Block: 256 threads, 64 rows x 128 cols. W tile (64KB) + A tile (34KB) in dynamic smem.
template<int RELU, int COLSUM>
__global__ __launch_bounds__(256, 2)
void gemm_ln_kernel(const float* __restrict__ A, const float* __restrict__ Wm,
                    const float* __restrict__ gamma, const float* __restrict__ beta,
                    float* __restrict__ Y, int Nrows)
{
    extern __shared__ float sh[];
    float* sW = sh;              // 128*128
    float* sA = sh + CC*CC;      // 64 rows, stride 136 (pad 8 avoids bank conflicts)
    const int tid  = threadIdx.x;
    const int lane = tid & 31, wrp = tid >> 5;

    // load W (128x128) cooperatively
    {
        const float4* Wv = (const float4*)Wm;
        float4* sWv = (float4*)sW;
        #pragma unroll 4
        for (int i = tid; i < CC*CC/4; i += 256) sWv[i] = Wv[i];
    }
    const int i0 = blockIdx.x * TM;
    // load A tile 64x128 (row-major, stride 136)
    #pragma unroll
    for (int m = 0; m < 8; m++) {
        int row = wrp*8 + m;
        int gr = i0 + row;
        float4 v = (gr < Nrows) ? ((const float4*)A)[(size_t)gr*32 + lane]
                                : make_float4(0.f,0.f,0.f,0.f);
        *(float4*)&sA[row*136 + lane*4] = v;
    }
    __syncthreads();

    const int colg = tid & 15, rowg = tid >> 4;
    const int col0 = colg*8, row0 = rowg*4;
    float acc[4][8];
    #pragma unroll
    for (int r = 0; r < 4; r++)
        #pragma unroll
        for (int c = 0; c < 8; c++) acc[r][c] = 0.f;

    #pragma unroll 2
    for (int k = 0; k < CC; k += 4) {
        float4 a4[4];
        #pragma unroll
        for (int r = 0; r < 4; r++) a4[r] = *(float4*)&sA[(row0+r)*136 + k];
        #pragma unroll
        for (int kk = 0; kk < 4; kk++) {
            float4 b0 = *(float4*)&sW[(k+kk)*CC + col0];
            float4 b1 = *(float4*)&sW[(k+kk)*CC + col0 + 4];
            #pragma unroll
            for (int r = 0; r < 4; r++) {
                float a = (&a4[r].x)[kk];
                acc[r][0] += a*b0.x; acc[r][1] += a*b0.y;
                acc[r][2] += a*b0.z; acc[r][3] += a*b0.w;
                acc[r][4] += a*b1.x; acc[r][5] += a*b1.y;
                acc[r][6] += a*b1.z; acc[r][7] += a*b1.w;
            }
        }
    }
    __syncthreads();
    // stage results back into sA (reuse)
    #pragma unroll
    for (int r = 0; r < 4; r++) {
        *(float4*)&sA[(row0+r)*136 + col0]     = make_float4(acc[r][0],acc[r][1],acc[r][2],acc[r][3]);
        *(float4*)&sA[(row0+r)*136 + col0 + 4] = make_float4(acc[r][4],acc[r][5],acc[r][6],acc[r][7]);
    }
    if (COLSUM && tid < CC) sW[tid] = 0.f;   // sW no longer needed; reuse as reduction buffer
    __syncthreads();

    // LayerNorm: warp per row (8 rows per warp), lane owns cols lane+32j
    float csum[4] = {0.f,0.f,0.f,0.f};
    float gamv[4], betv[4];
    #pragma unroll
    for (int j = 0; j < 4; j++) { gamv[j] = gamma[lane+32*j]; betv[j] = beta[lane+32*j]; }

    #pragma unroll
    for (int m = 0; m < 8; m++) {
        int row = wrp*8 + m;
        int gr = i0 + row;
        if (gr >= Nrows) break;   // uniform across warp
        float x[4];
        #pragma unroll
        for (int j = 0; j < 4; j++) x[j] = sA[row*136 + lane + 32*j];
        float s  = x[0]+x[1]+x[2]+x[3];
        float s2 = x[0]*x[0]+x[1]*x[1]+x[2]*x[2]+x[3]*x[3];
        #pragma unroll
        for (int o = 16; o > 0; o >>= 1) {
            s  += __shfl_xor_sync(0xffffffffu, s,  o);
            s2 += __shfl_xor_sync(0xffffffffu, s2, o);
        }
        float mu  = s * (1.f/128.f);
        float var = s2 * (1.f/128.f) - mu*mu;
        float rs  = rsqrtf(var + 1e-5f);
        #pragma unroll
        for (int j = 0; j < 4; j++) {
            float y = (x[j]-mu)*rs*gamv[j] + betv[j];
            if (RELU) y = fmaxf(y, 0.f);
            Y[(size_t)gr*CC + lane + 32*j] = y;
            if (COLSUM) csum[j] += y;
        }
    }
    if (COLSUM) {
        __syncthreads();
        #pragma unroll
        for (int j = 0; j < 4; j++) atomicAdd(&sW[lane + 32*j], csum[j]);
        __syncthreads();
        if (tid < CC) atomicAdd(&g_colsum[tid], sW[tid]);
    }
}

// ---------------- SE gate: mean -> fc(128->32) relu -> fc(32->128) sigmoid ----------------
__global__ void se_kernel(const float* __restrict__ w1, const float* __restrict__ b1,
                          const float* __restrict__ w2, const float* __restrict__ b2,
                          float invN)
{
    __shared__ float sq[CC];
    __shared__ float h[32];
    int t = threadIdx.x;
    sq[t] = g_colsum[t] * invN;
    __syncthreads();
    if (t < 32) {
        float a = b1[t];
        #pragma unroll 4
        for (int c = 0; c < CC; c++) a += sq[c] * w1[c*32 + t];
        h[t] = fmaxf(a, 0.f);
    }
    __syncthreads();
    float a = b2[t];
    #pragma unroll
    for (int j = 0; j < 32; j++) a += h[j] * w2[j*CC + t];
    g_scale[t] = 1.f / (1.f + expf(-a));
}

// ---------------- unique via bitmap + rank ----------------
__global__ void bitmap_kernel(const int* __restrict__ idx, int Nrows) {
    int i = blockIdx.x * blockDim.x + threadIdx.x;
    if (i >= Nrows) return;
    int4 v = ((const int4*)idx)[i];
    unsigned lin = (unsigned)(v.x*STRIDE_Bc + v.y*STRIDE_Tc + v.z*STRIDE_Hc + v.w);
    atomicOr(&g_bitmap[lin >> 5], 1u << (lin & 31));
}

__global__ void scan1_kernel() {   // per-1024-word block popcount sums
    int b = blockIdx.x, t = threadIdx.x;
    unsigned base = b * 1024;
    unsigned s = 0;
    #pragma unroll
    for (int j = 0; j < 4; j++) s += __popc(g_bitmap[base + t*4 + j]);
    #pragma unroll
    for (int o = 16; o > 0; o >>= 1) s += __shfl_xor_sync(0xffffffffu, s, o);
    __shared__ unsigned ws[8];
    if ((t & 31) == 0) ws[t >> 5] = s;
    __syncthreads();
    if (t == 0) {
        unsigned tot = 0;
        #pragma unroll
        for (int w = 0; w < 8; w++) tot += ws[w];
        g_blocksum[b] = tot;
    }
}

__global__ void scan2_kernel() {   // exclusive scan of 1024 block sums
    int t = threadIdx.x, lane = t & 31, w = t >> 5;
    unsigned v = g_blocksum[t];
    unsigned x = v;
    #pragma unroll
    for (int o = 1; o < 32; o <<= 1) {
        unsigned n = __shfl_up_sync(0xffffffffu, x, o);
        if (lane >= o) x += n;
    }
    __shared__ unsigned ws[32];
    if (lane == 31) ws[w] = x;
    __syncthreads();
    if (w == 0) {
        unsigned y = ws[lane];
        #pragma unroll
        for (int o = 1; o < 32; o <<= 1) {
            unsigned n = __shfl_up_sync(0xffffffffu, y, o);
            if (lane >= o) y += n;
        }
        ws[lane] = y;
    }
    __syncthreads();
    unsigned incl = x + (w ? ws[w-1] : 0u);
    g_blockoff[t] = incl - v;
    if (t == 1023) g_U = incl;
}

__global__ void scan3_kernel() {   // per-word global exclusive rank
    int b = blockIdx.x, t = threadIdx.x, lane = t & 31, w = t >> 5;
    unsigned base = b * 1024;
    unsigned wd[4];
    unsigned s = 0;
    #pragma unroll
    for (int j = 0; j < 4; j++) { wd[j] = g_bitmap[base + t*4 + j]; s += __popc(wd[j]); }
    unsigned x = s;
    #pragma unroll
    for (int o = 1; o < 32; o <<= 1) {
        unsigned n = __shfl_up_sync(0xffffffffu, x, o);
        if (lane >= o) x += n;
    }
    __shared__ unsigned ws[8];
    if (lane == 31) ws[w] = x;
    __syncthreads();
    if (t == 0) {
        unsigned acc = 0;
        #pragma unroll
        for (int i = 0; i < 8; i++) { unsigned tmp = ws[i]; ws[i] = acc; acc += tmp; }
    }
    __syncthreads();
    unsigned run = ws[w] + (x - s) + g_blockoff[b];
    #pragma unroll
    for (int j = 0; j < 4; j++) {
        g_wordscan[base + t*4 + j] = run;
        run += __popc(wd[j]);
    }
}

// ---------------- scatter-add: merged[rank] += out*scale + feats ----------------
__global__ void scatter_kernel(const float* __restrict__ feats, const int* __restrict__ idx,
                               float* __restrict__ outM, float* __restrict__ outIdx,
                               int hasIdx, int Nrows)
{
    int lane = threadIdx.x & 31, w = threadIdx.x >> 5;
    int row = blockIdx.x * 8 + w;
    if (row >= Nrows) return;
    int4 iv = ((const int4*)idx)[row];
    unsigned lin = (unsigned)(iv.x*STRIDE_Bc + iv.y*STRIDE_Tc + iv.z*STRIDE_Hc + iv.w);
    unsigned wo = lin >> 5, bit = lin & 31;
    unsigned r = g_wordscan[wo] + __popc(g_bitmap[wo] & ((1u << bit) - 1u));

    float4 v  = ((const float4*)g_X2)[(size_t)row*32 + lane];
    float4 f  = ((const float4*)feats)[(size_t)row*32 + lane];
    float4 sc = ((const float4*)g_scale)[lane];
    float4 o;
    o.x = v.x*sc.x + f.x;
    o.y = v.y*sc.y + f.y;
    o.z = v.z*sc.z + f.z;
    o.w = v.w*sc.w + f.w;
    float* dst = &outM[(size_t)r*CC + lane*4];
    atomicAdd(dst+0, o.x); atomicAdd(dst+1, o.y);
    atomicAdd(dst+2, o.z); atomicAdd(dst+3, o.w);

    if (hasIdx && lane == 0) {
        ((float4*)outIdx)[r] = make_float4((float)iv.x, (float)iv.y, (float)iv.z, (float)iv.w);
    }
}

// ---------------- finalize: valid mask, relu, sentinel index rows ----------------
__global__ void finalize_kernel(float* __restrict__ outM, float* __restrict__ outIdx,
                                float* __restrict__ outValid,
                                int hasIdx, int hasValid, int Mrows)
{
    int lane = threadIdx.x & 31, w = threadIdx.x >> 5;
    int row = blockIdx.x * 8 + w;
    if (row >= Mrows) return;
    float4* p = (float4*)outM + (size_t)row*32 + lane;
    float4 v = *p;
    float s = fabsf(v.x) + fabsf(v.y) + fabsf(v.z) + fabsf(v.w);
    #pragma unroll
    for (int o = 16; o > 0; o >>= 1) s += __shfl_xor_sync(0xffffffffu, s, o);
    bool valid = (s > 1e-8f);
    float4 ov;
    if (valid) {
        ov.x = fmaxf(v.x, 0.f); ov.y = fmaxf(v.y, 0.f);
        ov.z = fmaxf(v.z, 0.f); ov.w = fmaxf(v.w, 0.f);
    } else {
        ov = make_float4(0.f, 0.f, 0.f, 0.f);
    }
    *p = ov;
    if (lane == 0) {
        if (hasValid) outValid[row] = valid ? 1.f : 0.f;
        if (hasIdx && (unsigned)row >= g_U)
            ((float4*)outIdx)[row] = make_float4(8.f, 0.f, 0.f, 0.f);
    }
}

// ---------------- launch ----------------
extern "C" void kernel_launch(void* const* d_in, const int* in_sizes, int n_in,
                              void* d_out, int out_size)
{
    const float* feats = (const float*)d_in[0];
    const int*   indices = (const int*)d_in[1];
    const float* W1   = (const float*)d_in[2];
    const float* ln1g = (const float*)d_in[3];
    const float* ln1b = (const float*)d_in[4];
    const float* W2   = (const float*)d_in[5];
    const float* ln2g = (const float*)d_in[6];
    const float* ln2b = (const float*)d_in[7];
    const float* sew1 = (const float*)d_in[8];
    const float* seb1 = (const float*)d_in[9];
    const float* sew2 = (const float*)d_in[10];
    const float* seb2 = (const float*)d_in[11];

    int Nr = in_sizes[0] / CC;
    int M  = 2 * Nr;

    float* outM = (float*)d_out;
    long long osz = (long long)out_size;
    int hasIdx   = osz >= (long long)M * (CC + 4);
    int hasValid = osz >= (long long)M * (CC + 5);
    float* outIdx   = outM + (size_t)M * CC;
    float* outValid = outIdx + (hasIdx ? (size_t)M * 4 : 0);

    void *px1 = nullptr, *px2 = nullptr;
    cudaGetSymbolAddress(&px1, g_X1);
    cudaGetSymbolAddress(&px2, g_X2);

    size_t smem = (size_t)(CC*CC + TM*136) * sizeof(float);
    cudaFuncSetAttribute(gemm_ln_kernel<1,0>, cudaFuncAttributeMaxDynamicSharedMemorySize, (int)smem);
    cudaFuncSetAttribute(gemm_ln_kernel<0,1>, cudaFuncAttributeMaxDynamicSharedMemorySize, (int)smem);

    cudaMemsetAsync(d_out, 0, (size_t)out_size * sizeof(float));
    zero_kernel<<<2048, 256>>>();

    int gb = (Nr + TM - 1) / TM;
    gemm_ln_kernel<1,0><<<gb, 256, smem>>>(feats, W1, ln1g, ln1b, (float*)px1, Nr);
    gemm_ln_kernel<0,1><<<gb, 256, smem>>>((const float*)px1, W2, ln2g, ln2b, (float*)px2, Nr);
    se_kernel<<<1, CC>>>(sew1, seb1, sew2, seb2, 1.0f / (float)Nr);

    bitmap_kernel<<<(Nr + 255) / 256, 256>>>(indices, Nr);
    scan1_kernel<<<1024, 256>>>();
    scan2_kernel<<<1, 1024>>>();
    scan3_kernel<<<1024, 256>>>();

    scatter_kernel<<<(Nr + 7) / 8, 256>>>(feats, indices, outM, outIdx, hasIdx, Nr);
    finalize_kernel<<<(M + 7) / 8, 256>>>(outM, outIdx, outValid, hasIdx, hasValid, M);
}

// round 3
// speedup vs baseline: 1.4493x; 1.4493x over previous
#include <cuda_runtime.h>
#include <cuda_bf16.h>
#include <math.h>
#include <stdint.h>

#define CC 128
#define NMAX 300000
#define NWORDS (1u<<20)
#define STRIDE_Bc 4194304
#define STRIDE_Tc 262144
#define STRIDE_Hc 512

// ================= device scratch =================
__device__ uint32_t g_Y1hi[(size_t)NMAX*64];   // bf16x2 packed, [row][64]
__device__ uint32_t g_Y1lo[(size_t)NMAX*64];
__device__ float    g_X2[(size_t)NMAX*CC];
__device__ unsigned g_bitmap[NWORDS];
__device__ unsigned g_wordscan[NWORDS];
__device__ unsigned g_blocksum[1024];
__device__ unsigned g_blockoff[1024];
__device__ unsigned g_U;
__device__ float    g_colsum[CC];
__device__ float    g_scale[CC];

// ================= helpers =================
__device__ __forceinline__ uint32_t smem_u32(const void* p){
    uint32_t a;
    asm("{ .reg .u64 t; cvta.to.shared.u64 t, %1; cvt.u32.u64 %0, t; }" : "=r"(a) : "l"(p));
    return a;
}

__device__ __forceinline__ void ldsm_x4(uint32_t addr, uint32_t& r0, uint32_t& r1,
                                        uint32_t& r2, uint32_t& r3){
    asm volatile("ldmatrix.sync.aligned.m8n8.x4.shared.b16 {%0,%1,%2,%3}, [%4];"
        : "=r"(r0),"=r"(r1),"=r"(r2),"=r"(r3) : "r"(addr));
}

__device__ __forceinline__ void mma_bf16(float* d, const uint32_t* a, uint32_t b0, uint32_t b1){
    asm volatile("mma.sync.aligned.m16n8k16.row.col.f32.bf16.bf16.f32 "
        "{%0,%1,%2,%3}, {%4,%5,%6,%7}, {%8,%9}, {%0,%1,%2,%3};"
        : "+f"(d[0]),"+f"(d[1]),"+f"(d[2]),"+f"(d[3])
        : "r"(a[0]),"r"(a[1]),"r"(a[2]),"r"(a[3]), "r"(b0),"r"(b1));
}

__device__ __forceinline__ void split2(float a, float b, uint32_t& hi, uint32_t& lo){
    __nv_bfloat162 h = __floats2bfloat162_rn(a, b);   // .x (=a) in low 16 bits
    hi = *reinterpret_cast<uint32_t*>(&h);
    float ra = a - __bfloat162float(h.x);
    float rb = b - __bfloat162float(h.y);
    __nv_bfloat162 l = __floats2bfloat162_rn(ra, rb);
    lo = *reinterpret_cast<uint32_t*>(&l);
}

// SMEM layout for GEMM kernels
#define SW        136               // padded row stride (elements) -> conflict-free LDSM
#define OFF_GAMMA 0
#define OFF_BETA  512
#define OFF_WHI   1024
#define OFF_WLO   (1024 + 128*SW*2)           // 35840
#define SMEM_GEMM (OFF_WLO + 128*SW*2)        // 70656

__device__ __forceinline__ void load_W_split(char* smem, const float* __restrict__ Wm, int tid){
    __nv_bfloat16* sWhi = (__nv_bfloat16*)(smem + OFF_WHI);
    __nv_bfloat16* sWlo = (__nv_bfloat16*)(smem + OFF_WLO);
    // B[n][k] = W[k][n]; thread owns n = tid, loop over k (coalesced global reads)
    #pragma unroll 4
    for (int k = 0; k < CC; k++){
        float w = Wm[k*CC + tid];
        __nv_bfloat16 h = __float2bfloat16(w);
        float r = w - __bfloat162float(h);
        sWhi[tid*SW + k] = h;
        sWlo[tid*SW + k] = __float2bfloat16(r);
    }
}

// One pass over a 16(rows)x128(cols)x128(k) block per warp, accumulating into acc.
__device__ __forceinline__ void do_pass(float (&acc)[16][4], const uint32_t (&Ar)[32],
                                        uint32_t wb, int belem){
    #pragma unroll
    for (int np = 0; np < 8; np++){
        #pragma unroll
        for (int ks = 0; ks < 8; ks++){
            uint32_t addr = wb + (uint32_t)((np*16*SW + ks*16 + belem) * 2);
            uint32_t b0,b1,b2,b3;
            ldsm_x4(addr, b0, b1, b2, b3);
            mma_bf16(acc[np*2],   Ar + ks*4, b0, b1);
            mma_bf16(acc[np*2+1], Ar + ks*4, b2, b3);
        }
    }
}

// ================= GEMM1: feats(f32) @ W1 -> LN -> ReLU -> bf16 hi/lo =================
__global__ __launch_bounds__(128, 3)
void gemm1_kernel(const float* __restrict__ A, const float* __restrict__ Wm,
                  const float* __restrict__ gamma, const float* __restrict__ beta,
                  uint32_t* __restrict__ Yhi, uint32_t* __restrict__ Ylo, int Nrows)
{
    extern __shared__ char smem[];
    uint32_t sb = smem_u32(smem);
    float* sGam = (float*)(smem + OFF_GAMMA);
    float* sBet = (float*)(smem + OFF_BETA);
    const int tid = threadIdx.x, lane = tid & 31, wid = tid >> 5;
    const int q = lane & 3, rq = lane >> 2;
    // ldmatrix lane->row/col: matrices m0..m3 = (nLo,kLo),(nLo,kHi),(nHi,kLo),(nHi,kHi)
    const int jj = lane >> 3, rr = lane & 7;
    const int belem = ((jj >= 2 ? 8 : 0) + rr) * SW + ((jj & 1) ? 8 : 0);

    sGam[tid] = gamma[tid];
    sBet[tid] = beta[tid];
    load_W_split(smem, Wm, tid);
    __syncthreads();

    const int NT = (Nrows + 63) >> 6;
    for (int tile = blockIdx.x; tile < NT; tile += gridDim.x){
        const int r0 = tile*64 + wid*16 + rq;
        const bool ok0 = r0 < Nrows, ok1 = (r0 + 8) < Nrows;
        const float* pA0 = A + (size_t)r0 * CC;
        const float* pA1 = pA0 + 8 * CC;

        uint32_t Ahi[32], Alo[32];
        #pragma unroll
        for (int ks = 0; ks < 8; ks++){
            int k0 = ks*16 + 2*q;
            float2 z = make_float2(0.f, 0.f);
            float2 f0 = ok0 ? *(const float2*)(pA0 + k0)     : z;
            float2 f1 = ok1 ? *(const float2*)(pA1 + k0)     : z;
            float2 f2 = ok0 ? *(const float2*)(pA0 + k0 + 8) : z;
            float2 f3 = ok1 ? *(const float2*)(pA1 + k0 + 8) : z;
            split2(f0.x, f0.y, Ahi[ks*4+0], Alo[ks*4+0]);
            split2(f1.x, f1.y, Ahi[ks*4+1], Alo[ks*4+1]);
            split2(f2.x, f2.y, Ahi[ks*4+2], Alo[ks*4+2]);
            split2(f3.x, f3.y, Ahi[ks*4+3], Alo[ks*4+3]);
        }

        float acc[16][4];
        #pragma unroll
        for (int t = 0; t < 16; t++)
            #pragma unroll
            for (int j = 0; j < 4; j++) acc[t][j] = 0.f;

        do_pass(acc, Ahi, sb + OFF_WHI, belem);
        do_pass(acc, Ahi, sb + OFF_WLO, belem);
        do_pass(acc, Alo, sb + OFF_WHI, belem);

        // LayerNorm per row (quad reduction), then ReLU + bf16 split store
        float s0=0.f, q0=0.f, s1=0.f, q1=0.f;
        #pragma unroll
        for (int t = 0; t < 16; t++){
            s0 += acc[t][0] + acc[t][1];
            q0 += acc[t][0]*acc[t][0] + acc[t][1]*acc[t][1];
            s1 += acc[t][2] + acc[t][3];
            q1 += acc[t][2]*acc[t][2] + acc[t][3]*acc[t][3];
        }
        #pragma unroll
        for (int o = 1; o <= 2; o <<= 1){
            s0 += __shfl_xor_sync(0xffffffffu, s0, o);
            q0 += __shfl_xor_sync(0xffffffffu, q0, o);
            s1 += __shfl_xor_sync(0xffffffffu, s1, o);
            q1 += __shfl_xor_sync(0xffffffffu, q1, o);
        }
        float mu0 = s0*(1.f/128.f), mu1 = s1*(1.f/128.f);
        float rs0 = rsqrtf(q0*(1.f/128.f) - mu0*mu0 + 1e-5f);
        float rs1 = rsqrtf(q1*(1.f/128.f) - mu1*mu1 + 1e-5f);

        uint32_t* yh0 = Yhi + (size_t)r0*64 + q;
        uint32_t* yl0 = Ylo + (size_t)r0*64 + q;
        uint32_t* yh1 = yh0 + 8*64;
        uint32_t* yl1 = yl0 + 8*64;
        #pragma unroll
        for (int t = 0; t < 16; t++){
            int c = t*8 + 2*q;
            float g0 = sGam[c], g1 = sGam[c+1], b0 = sBet[c], b1 = sBet[c+1];
            if (ok0){
                float y0 = fmaxf((acc[t][0]-mu0)*rs0*g0 + b0, 0.f);
                float y1 = fmaxf((acc[t][1]-mu0)*rs0*g1 + b1, 0.f);
                uint32_t h, l; split2(y0, y1, h, l);
                yh0[t*4] = h; yl0[t*4] = l;
            }
            if (ok1){
                float y0 = fmaxf((acc[t][2]-mu1)*rs1*g0 + b0, 0.f);
                float y1 = fmaxf((acc[t][3]-mu1)*rs1*g1 + b1, 0.f);
                uint32_t h, l; split2(y0, y1, h, l);
                yh1[t*4] = h; yl1[t*4] = l;
            }
        }
    }
}

// ================= GEMM2: Y1(bf16 hi/lo) @ W2 -> LN -> X2(f32) + colsum =================
__global__ __launch_bounds__(128, 3)
void gemm2_kernel(const uint32_t* __restrict__ Yhi, const uint32_t* __restrict__ Ylo,
                  const float* __restrict__ Wm,
                  const float* __restrict__ gamma, const float* __restrict__ beta,
                  float* __restrict__ X2, int Nrows)
{
    extern __shared__ char smem[];
    uint32_t sb = smem_u32(smem);
    float* sGam = (float*)(smem + OFF_GAMMA);
    float* sBet = (float*)(smem + OFF_BETA);
    const int tid = threadIdx.x, lane = tid & 31, wid = tid >> 5;
    const int q = lane & 3, rq = lane >> 2;
    const int jj = lane >> 3, rr = lane & 7;
    const int belem = ((jj >= 2 ? 8 : 0) + rr) * SW + ((jj & 1) ? 8 : 0);

    sGam[tid] = gamma[tid];
    sBet[tid] = beta[tid];
    load_W_split(smem, Wm, tid);
    __syncthreads();

    float csum[32];
    #pragma unroll
    for (int j = 0; j < 32; j++) csum[j] = 0.f;

    const int NT = (Nrows + 63) >> 6;
    for (int tile = blockIdx.x; tile < NT; tile += gridDim.x){
        const int r0 = tile*64 + wid*16 + rq;
        const bool ok0 = r0 < Nrows, ok1 = (r0 + 8) < Nrows;
        const uint32_t* ph0 = Yhi + (size_t)r0*64;
        const uint32_t* ph1 = ph0 + 8*64;
        const uint32_t* pl0 = Ylo + (size_t)r0*64;
        const uint32_t* pl1 = pl0 + 8*64;

        uint32_t Ahi[32], Alo[32];
        #pragma unroll
        for (int ks = 0; ks < 8; ks++){
            int i0 = ks*8 + q;
            Ahi[ks*4+0] = ok0 ? ph0[i0]     : 0u;
            Ahi[ks*4+1] = ok1 ? ph1[i0]     : 0u;
            Ahi[ks*4+2] = ok0 ? ph0[i0 + 4] : 0u;
            Ahi[ks*4+3] = ok1 ? ph1[i0 + 4] : 0u;
            Alo[ks*4+0] = ok0 ? pl0[i0]     : 0u;
            Alo[ks*4+1] = ok1 ? pl1[i0]     : 0u;
            Alo[ks*4+2] = ok0 ? pl0[i0 + 4] : 0u;
            Alo[ks*4+3] = ok1 ? pl1[i0 + 4] : 0u;
        }

        float acc[16][4];
        #pragma unroll
        for (int t = 0; t < 16; t++)
            #pragma unroll
            for (int j = 0; j < 4; j++) acc[t][j] = 0.f;

        do_pass(acc, Ahi, sb + OFF_WHI, belem);
        do_pass(acc, Ahi, sb + OFF_WLO, belem);
        do_pass(acc, Alo, sb + OFF_WHI, belem);

        float s0=0.f, q0=0.f, s1=0.f, q1=0.f;
        #pragma unroll
        for (int t = 0; t < 16; t++){
            s0 += acc[t][0] + acc[t][1];
            q0 += acc[t][0]*acc[t][0] + acc[t][1]*acc[t][1];
            s1 += acc[t][2] + acc[t][3];
            q1 += acc[t][2]*acc[t][2] + acc[t][3]*acc[t][3];
        }
        #pragma unroll
        for (int o = 1; o <= 2; o <<= 1){
            s0 += __shfl_xor_sync(0xffffffffu, s0, o);
            q0 += __shfl_xor_sync(0xffffffffu, q0, o);
            s1 += __shfl_xor_sync(0xffffffffu, s1, o);
            q1 += __shfl_xor_sync(0xffffffffu, q1, o);
        }
        float mu0 = s0*(1.f/128.f), mu1 = s1*(1.f/128.f);
        float rs0 = rsqrtf(q0*(1.f/128.f) - mu0*mu0 + 1e-5f);
        float rs1 = rsqrtf(q1*(1.f/128.f) - mu1*mu1 + 1e-5f);

        float* px0 = X2 + (size_t)r0*CC + 2*q;
        float* px1 = px0 + 8*CC;
        #pragma unroll
        for (int t = 0; t < 16; t++){
            int c = t*8 + 2*q;
            float g0 = sGam[c], g1 = sGam[c+1], b0 = sBet[c], b1 = sBet[c+1];
            if (ok0){
                float y0 = (acc[t][0]-mu0)*rs0*g0 + b0;
                float y1 = (acc[t][1]-mu0)*rs0*g1 + b1;
                *(float2*)(px0 + t*8) = make_float2(y0, y1);
                csum[t*2]   += y0;
                csum[t*2+1] += y1;
            }
            if (ok1){
                float y0 = (acc[t][2]-mu1)*rs1*g0 + b0;
                float y1 = (acc[t][3]-mu1)*rs1*g1 + b1;
                *(float2*)(px1 + t*8) = make_float2(y0, y1);
                csum[t*2]   += y0;
                csum[t*2+1] += y1;
            }
        }
    }

    // reduce csum across lanes that share q (xor 4, 8, 16), then one atomicAdd set
    #pragma unroll
    for (int j = 0; j < 32; j++){
        float v = csum[j];
        v += __shfl_xor_sync(0xffffffffu, v, 4);
        v += __shfl_xor_sync(0xffffffffu, v, 8);
        v += __shfl_xor_sync(0xffffffffu, v, 16);
        csum[j] = v;
    }
    if (lane < 4){
        #pragma unroll
        for (int t = 0; t < 16; t++){
            atomicAdd(&g_colsum[t*8 + 2*lane],     csum[t*2]);
            atomicAdd(&g_colsum[t*8 + 2*lane + 1], csum[t*2+1]);
        }
    }
}

// ================= zero per-iteration state =================
__global__ void zero_kernel() {
    unsigned i = blockIdx.x * blockDim.x + threadIdx.x;
    unsigned stride = gridDim.x * blockDim.x;
    for (unsigned w = i; w < NWORDS; w += stride) g_bitmap[w] = 0u;
    if (i < CC) g_colsum[i] = 0.f;
}

// ================= SE gate =================
__global__ void se_kernel(const float* __restrict__ w1, const float* __restrict__ b1,
                          const float* __restrict__ w2, const float* __restrict__ b2,
                          float invN)
{
    __shared__ float sq[CC];
    __shared__ float hp[4][32];
    __shared__ float h[32];
    int t = threadIdx.x;
    sq[t] = g_colsum[t] * invN;
    __syncthreads();
    int j = t & 31, grp = t >> 5;
    float a = 0.f;
    #pragma unroll 8
    for (int c = 0; c < 32; c++){
        int cc = grp*32 + c;
        a += sq[cc] * w1[cc*32 + j];
    }
    hp[grp][j] = a;
    __syncthreads();
    if (t < 32){
        float v = b1[t] + hp[0][t] + hp[1][t] + hp[2][t] + hp[3][t];
        h[t] = fmaxf(v, 0.f);
    }
    __syncthreads();
    float o = b2[t];
    #pragma unroll
    for (int jj = 0; jj < 32; jj++) o += h[jj] * w2[jj*CC + t];
    g_scale[t] = 1.f / (1.f + expf(-o));
}

// ================= unique via bitmap + rank =================
__global__ void bitmap_kernel(const int* __restrict__ idx, int Nrows) {
    int i = blockIdx.x * blockDim.x + threadIdx.x;
    if (i >= Nrows) return;
    int4 v = ((const int4*)idx)[i];
    unsigned lin = (unsigned)(v.x*STRIDE_Bc + v.y*STRIDE_Tc + v.z*STRIDE_Hc + v.w);
    atomicOr(&g_bitmap[lin >> 5], 1u << (lin & 31));
}

__global__ void scan1_kernel() {
    int b = blockIdx.x, t = threadIdx.x;
    unsigned base = b * 1024;
    unsigned s = 0;
    #pragma unroll
    for (int j = 0; j < 4; j++) s += __popc(g_bitmap[base + t*4 + j]);
    #pragma unroll
    for (int o = 16; o > 0; o >>= 1) s += __shfl_xor_sync(0xffffffffu, s, o);
    __shared__ unsigned ws[8];
    if ((t & 31) == 0) ws[t >> 5] = s;
    __syncthreads();
    if (t == 0) {
        unsigned tot = 0;
        #pragma unroll
        for (int w = 0; w < 8; w++) tot += ws[w];
        g_blocksum[b] = tot;
    }
}

__global__ void scan2_kernel() {
    int t = threadIdx.x, lane = t & 31, w = t >> 5;
    unsigned v = g_blocksum[t];
    unsigned x = v;
    #pragma unroll
    for (int o = 1; o < 32; o <<= 1) {
        unsigned n = __shfl_up_sync(0xffffffffu, x, o);
        if (lane >= o) x += n;
    }
    __shared__ unsigned ws[32];
    if (lane == 31) ws[w] = x;
    __syncthreads();
    if (w == 0) {
        unsigned y = ws[lane];
        #pragma unroll
        for (int o = 1; o < 32; o <<= 1) {
            unsigned n = __shfl_up_sync(0xffffffffu, y, o);
            if (lane >= o) y += n;
        }
        ws[lane] = y;
    }
    __syncthreads();
    unsigned incl = x + (w ? ws[w-1] : 0u);
    g_blockoff[t] = incl - v;
    if (t == 1023) g_U = incl;
}

__global__ void scan3_kernel() {
    int b = blockIdx.x, t = threadIdx.x, lane = t & 31, w = t >> 5;
    unsigned base = b * 1024;
    unsigned wd[4];
    unsigned s = 0;
    #pragma unroll
    for (int j = 0; j < 4; j++) { wd[j] = g_bitmap[base + t*4 + j]; s += __popc(wd[j]); }
    unsigned x = s;
    #pragma unroll
    for (int o = 1; o < 32; o <<= 1) {
        unsigned n = __shfl_up_sync(0xffffffffu, x, o);
        if (lane >= o) x += n;
    }
    __shared__ unsigned ws[8];
    if (lane == 31) ws[w] = x;
    __syncthreads();
    if (t == 0) {
        unsigned acc = 0;
        #pragma unroll
        for (int i = 0; i < 8; i++) { unsigned tmp = ws[i]; ws[i] = acc; acc += tmp; }
    }
    __syncthreads();
    unsigned run = ws[w] + (x - s) + g_blockoff[b];
    #pragma unroll
    for (int j = 0; j < 4; j++) {
        g_wordscan[base + t*4 + j] = run;
        run += __popc(wd[j]);
    }
}

// ================= scatter-add =================
__global__ void scatter_kernel(const float* __restrict__ feats, const int* __restrict__ idx,
                               float* __restrict__ outM, float* __restrict__ outIdx,
                               int hasIdx, int Nrows)
{
    int lane = threadIdx.x & 31, w = threadIdx.x >> 5;
    int row = blockIdx.x * 8 + w;
    if (row >= Nrows) return;
    int4 iv = ((const int4*)idx)[row];
    unsigned lin = (unsigned)(iv.x*STRIDE_Bc + iv.y*STRIDE_Tc + iv.z*STRIDE_Hc + iv.w);
    unsigned wo = lin >> 5, bit = lin & 31;
    unsigned r = g_wordscan[wo] + __popc(g_bitmap[wo] & ((1u << bit) - 1u));

    float4 v  = ((const float4*)g_X2)[(size_t)row*32 + lane];
    float4 f  = ((const float4*)feats)[(size_t)row*32 + lane];
    float4 sc = ((const float4*)g_scale)[lane];
    float4 o;
    o.x = v.x*sc.x + f.x;
    o.y = v.y*sc.y + f.y;
    o.z = v.z*sc.z + f.z;
    o.w = v.w*sc.w + f.w;
    float* dst = &outM[(size_t)r*CC + lane*4];
    atomicAdd(dst+0, o.x); atomicAdd(dst+1, o.y);
    atomicAdd(dst+2, o.z); atomicAdd(dst+3, o.w);

    if (hasIdx && lane == 0) {
        ((float4*)outIdx)[r] = make_float4((float)iv.x, (float)iv.y, (float)iv.z, (float)iv.w);
    }
}

// ================= finalize =================
__global__ void finalize_kernel(float* __restrict__ outM, float* __restrict__ outIdx,
                                float* __restrict__ outValid,
                                int hasIdx, int hasValid, int Mrows)
{
    int lane = threadIdx.x & 31, w = threadIdx.x >> 5;
    int row = blockIdx.x * 8 + w;
    if (row >= Mrows) return;
    unsigned U = g_U;
    if ((unsigned)row >= U) {
        if (lane == 0) {
            if (hasValid) outValid[row] = 0.f;
            if (hasIdx) ((float4*)outIdx)[row] = make_float4(8.f, 0.f, 0.f, 0.f);
        }
        return;   // merged rows stay zero from memset
    }
    float4* p = (float4*)outM + (size_t)row*32 + lane;
    float4 v = *p;
    float s = fabsf(v.x) + fabsf(v.y) + fabsf(v.z) + fabsf(v.w);
    #pragma unroll
    for (int o = 16; o > 0; o >>= 1) s += __shfl_xor_sync(0xffffffffu, s, o);
    bool valid = (s > 1e-8f);
    float4 ov;
    if (valid) {
        ov.x = fmaxf(v.x, 0.f); ov.y = fmaxf(v.y, 0.f);
        ov.z = fmaxf(v.z, 0.f); ov.w = fmaxf(v.w, 0.f);
    } else {
        ov = make_float4(0.f, 0.f, 0.f, 0.f);
    }
    *p = ov;
    if (lane == 0 && hasValid) outValid[row] = valid ? 1.f : 0.f;
}

// ================= launch =================
extern "C" void kernel_launch(void* const* d_in, const int* in_sizes, int n_in,
                              void* d_out, int out_size)
{
    const float* feats = (const float*)d_in[0];
    const int*   indices = (const int*)d_in[1];
    const float* W1   = (const float*)d_in[2];
    const float* ln1g = (const float*)d_in[3];
    const float* ln1b = (const float*)d_in[4];
    const float* W2   = (const float*)d_in[5];
    const float* ln2g = (const float*)d_in[6];
    const float* ln2b = (const float*)d_in[7];
    const float* sew1 = (const float*)d_in[8];
    const float* seb1 = (const float*)d_in[9];
    const float* sew2 = (const float*)d_in[10];
    const float* seb2 = (const float*)d_in[11];

    int Nr = in_sizes[0] / CC;
    int M  = 2 * Nr;

    float* outM = (float*)d_out;
    long long osz = (long long)out_size;
    int hasIdx   = osz >= (long long)M * (CC + 4);
    int hasValid = osz >= (long long)M * (CC + 5);
    float* outIdx   = outM + (size_t)M * CC;
    float* outValid = outIdx + (hasIdx ? (size_t)M * 4 : 0);

    void *pyh = nullptr, *pyl = nullptr, *px2 = nullptr;
    cudaGetSymbolAddress(&pyh, g_Y1hi);
    cudaGetSymbolAddress(&pyl, g_Y1lo);
    cudaGetSymbolAddress(&px2, g_X2);

    cudaFuncSetAttribute(gemm1_kernel, cudaFuncAttributeMaxDynamicSharedMemorySize, SMEM_GEMM);
    cudaFuncSetAttribute(gemm2_kernel, cudaFuncAttributeMaxDynamicSharedMemorySize, SMEM_GEMM);

    cudaMemsetAsync(d_out, 0, (size_t)out_size * sizeof(float));
    zero_kernel<<<2048, 256>>>();

    gemm1_kernel<<<444, 128, SMEM_GEMM>>>(feats, W1, ln1g, ln1b,
                                          (uint32_t*)pyh, (uint32_t*)pyl, Nr);
    gemm2_kernel<<<444, 128, SMEM_GEMM>>>((const uint32_t*)pyh, (const uint32_t*)pyl,
                                          W2, ln2g, ln2b, (float*)px2, Nr);
    se_kernel<<<1, CC>>>(sew1, seb1, sew2, seb2, 1.0f / (float)Nr);

    bitmap_kernel<<<(Nr + 255) / 256, 256>>>(indices, Nr);
    scan1_kernel<<<1024, 256>>>();
    scan2_kernel<<<1, 1024>>>();
    scan3_kernel<<<1024, 256>>>();

    scatter_kernel<<<(Nr + 7) / 8, 256>>>(feats, indices, outM, outIdx, hasIdx, Nr);
    finalize_kernel<<<(M + 7) / 8, 256>>>(outM, outIdx, outValid, hasIdx, hasValid, M);
}

// round 4
// speedup vs baseline: 1.6661x; 1.1496x over previous
#include <cuda_runtime.h>
#include <cuda_bf16.h>
#include <math.h>
#include <stdint.h>

#define CC 128
#define NMAX 300000
#define NWORDS (1u<<20)
#define STRIDE_Bc 4194304
#define STRIDE_Tc 262144
#define STRIDE_Hc 512

// ================= device scratch =================
__device__ uint32_t g_Y1hi[(size_t)NMAX*64];   // bf16x2 packed, [row][64]
__device__ uint32_t g_Y1lo[(size_t)NMAX*64];
__device__ float    g_X2[(size_t)NMAX*CC];
__device__ unsigned g_bitmap[NWORDS];
__device__ unsigned g_dup[NWORDS];
__device__ unsigned g_wordscan[NWORDS];
__device__ unsigned g_blocksum[1024];
__device__ unsigned g_blockoff[1024];
__device__ unsigned g_U;
__device__ unsigned g_ndup;
__device__ unsigned g_duplist[NMAX];
__device__ float    g_colsum[CC];
__device__ float    g_scale[CC];

// ================= helpers =================
__device__ __forceinline__ uint32_t smem_u32(const void* p){
    uint32_t a;
    asm("{ .reg .u64 t; cvta.to.shared.u64 t, %1; cvt.u32.u64 %0, t; }" : "=r"(a) : "l"(p));
    return a;
}

__device__ __forceinline__ void ldsm_x4(uint32_t addr, uint32_t& r0, uint32_t& r1,
                                        uint32_t& r2, uint32_t& r3){
    asm volatile("ldmatrix.sync.aligned.m8n8.x4.shared.b16 {%0,%1,%2,%3}, [%4];"
        : "=r"(r0),"=r"(r1),"=r"(r2),"=r"(r3) : "r"(addr));
}

__device__ __forceinline__ void mma_bf16(float* d, const uint32_t* a, uint32_t b0, uint32_t b1){
    asm volatile("mma.sync.aligned.m16n8k16.row.col.f32.bf16.bf16.f32 "
        "{%0,%1,%2,%3}, {%4,%5,%6,%7}, {%8,%9}, {%0,%1,%2,%3};"
        : "+f"(d[0]),"+f"(d[1]),"+f"(d[2]),"+f"(d[3])
        : "r"(a[0]),"r"(a[1]),"r"(a[2]),"r"(a[3]), "r"(b0),"r"(b1));
}

__device__ __forceinline__ void split2(float a, float b, uint32_t& hi, uint32_t& lo){
    __nv_bfloat162 h = __floats2bfloat162_rn(a, b);
    hi = *reinterpret_cast<uint32_t*>(&h);
    float ra = a - __bfloat162float(h.x);
    float rb = b - __bfloat162float(h.y);
    __nv_bfloat162 l = __floats2bfloat162_rn(ra, rb);
    lo = *reinterpret_cast<uint32_t*>(&l);
}

// SMEM layout for GEMM kernels
#define SW        136
#define OFF_GAMMA 0
#define OFF_BETA  512
#define OFF_WHI   1024
#define OFF_WLO   (1024 + 128*SW*2)
#define SMEM_GEMM (OFF_WLO + 128*SW*2)

__device__ __forceinline__ void load_W_split(char* smem, const float* __restrict__ Wm, int tid){
    __nv_bfloat16* sWhi = (__nv_bfloat16*)(smem + OFF_WHI);
    __nv_bfloat16* sWlo = (__nv_bfloat16*)(smem + OFF_WLO);
    #pragma unroll 4
    for (int k = 0; k < CC; k++){
        float w = Wm[k*CC + tid];
        __nv_bfloat16 h = __float2bfloat16(w);
        float r = w - __bfloat162float(h);
        sWhi[tid*SW + k] = h;
        sWlo[tid*SW + k] = __float2bfloat16(r);
    }
}

__device__ __forceinline__ void do_pass(float (&acc)[16][4], const uint32_t (&Ar)[32],
                                        uint32_t wb, int belem){
    #pragma unroll
    for (int np = 0; np < 8; np++){
        #pragma unroll
        for (int ks = 0; ks < 8; ks++){
            uint32_t addr = wb + (uint32_t)((np*16*SW + ks*16 + belem) * 2);
            uint32_t b0,b1,b2,b3;
            ldsm_x4(addr, b0, b1, b2, b3);
            mma_bf16(acc[np*2],   Ar + ks*4, b0, b1);
            mma_bf16(acc[np*2+1], Ar + ks*4, b2, b3);
        }
    }
}

// ================= GEMM1 =================
__global__ __launch_bounds__(128, 3)
void gemm1_kernel(const float* __restrict__ A, const float* __restrict__ Wm,
                  const float* __restrict__ gamma, const float* __restrict__ beta,
                  uint32_t* __restrict__ Yhi, uint32_t* __restrict__ Ylo, int Nrows)
{
    extern __shared__ char smem[];
    uint32_t sb = smem_u32(smem);
    float* sGam = (float*)(smem + OFF_GAMMA);
    float* sBet = (float*)(smem + OFF_BETA);
    const int tid = threadIdx.x, lane = tid & 31, wid = tid >> 5;
    const int q = lane & 3, rq = lane >> 2;
    const int jj = lane >> 3, rr = lane & 7;
    const int belem = ((jj >= 2 ? 8 : 0) + rr) * SW + ((jj & 1) ? 8 : 0);

    sGam[tid] = gamma[tid];
    sBet[tid] = beta[tid];
    load_W_split(smem, Wm, tid);
    __syncthreads();

    const int NT = (Nrows + 63) >> 6;
    for (int tile = blockIdx.x; tile < NT; tile += gridDim.x){
        const int r0 = tile*64 + wid*16 + rq;
        const bool ok0 = r0 < Nrows, ok1 = (r0 + 8) < Nrows;
        const float* pA0 = A + (size_t)r0 * CC;
        const float* pA1 = pA0 + 8 * CC;

        uint32_t Ahi[32], Alo[32];
        #pragma unroll
        for (int ks = 0; ks < 8; ks++){
            int k0 = ks*16 + 2*q;
            float2 z = make_float2(0.f, 0.f);
            float2 f0 = ok0 ? *(const float2*)(pA0 + k0)     : z;
            float2 f1 = ok1 ? *(const float2*)(pA1 + k0)     : z;
            float2 f2 = ok0 ? *(const float2*)(pA0 + k0 + 8) : z;
            float2 f3 = ok1 ? *(const float2*)(pA1 + k0 + 8) : z;
            split2(f0.x, f0.y, Ahi[ks*4+0], Alo[ks*4+0]);
            split2(f1.x, f1.y, Ahi[ks*4+1], Alo[ks*4+1]);
            split2(f2.x, f2.y, Ahi[ks*4+2], Alo[ks*4+2]);
            split2(f3.x, f3.y, Ahi[ks*4+3], Alo[ks*4+3]);
        }

        float acc[16][4];
        #pragma unroll
        for (int t = 0; t < 16; t++)
            #pragma unroll
            for (int j = 0; j < 4; j++) acc[t][j] = 0.f;

        do_pass(acc, Ahi, sb + OFF_WHI, belem);
        do_pass(acc, Ahi, sb + OFF_WLO, belem);
        do_pass(acc, Alo, sb + OFF_WHI, belem);

        float s0=0.f, q0=0.f, s1=0.f, q1=0.f;
        #pragma unroll
        for (int t = 0; t < 16; t++){
            s0 += acc[t][0] + acc[t][1];
            q0 += acc[t][0]*acc[t][0] + acc[t][1]*acc[t][1];
            s1 += acc[t][2] + acc[t][3];
            q1 += acc[t][2]*acc[t][2] + acc[t][3]*acc[t][3];
        }
        #pragma unroll
        for (int o = 1; o <= 2; o <<= 1){
            s0 += __shfl_xor_sync(0xffffffffu, s0, o);
            q0 += __shfl_xor_sync(0xffffffffu, q0, o);
            s1 += __shfl_xor_sync(0xffffffffu, s1, o);
            q1 += __shfl_xor_sync(0xffffffffu, q1, o);
        }
        float mu0 = s0*(1.f/128.f), mu1 = s1*(1.f/128.f);
        float rs0 = rsqrtf(q0*(1.f/128.f) - mu0*mu0 + 1e-5f);
        float rs1 = rsqrtf(q1*(1.f/128.f) - mu1*mu1 + 1e-5f);

        uint32_t* yh0 = Yhi + (size_t)r0*64 + q;
        uint32_t* yl0 = Ylo + (size_t)r0*64 + q;
        uint32_t* yh1 = yh0 + 8*64;
        uint32_t* yl1 = yl0 + 8*64;
        #pragma unroll
        for (int t = 0; t < 16; t++){
            int c = t*8 + 2*q;
            float g0 = sGam[c], g1 = sGam[c+1], b0 = sBet[c], b1 = sBet[c+1];
            if (ok0){
                float y0 = fmaxf((acc[t][0]-mu0)*rs0*g0 + b0, 0.f);
                float y1 = fmaxf((acc[t][1]-mu0)*rs0*g1 + b1, 0.f);
                uint32_t h, l; split2(y0, y1, h, l);
                yh0[t*4] = h; yl0[t*4] = l;
            }
            if (ok1){
                float y0 = fmaxf((acc[t][2]-mu1)*rs1*g0 + b0, 0.f);
                float y1 = fmaxf((acc[t][3]-mu1)*rs1*g1 + b1, 0.f);
                uint32_t h, l; split2(y0, y1, h, l);
                yh1[t*4] = h; yl1[t*4] = l;
            }
        }
    }
}

// ================= GEMM2 =================
__global__ __launch_bounds__(128, 3)
void gemm2_kernel(const uint32_t* __restrict__ Yhi, const uint32_t* __restrict__ Ylo,
                  const float* __restrict__ Wm,
                  const float* __restrict__ gamma, const float* __restrict__ beta,
                  float* __restrict__ X2, int Nrows)
{
    extern __shared__ char smem[];
    uint32_t sb = smem_u32(smem);
    float* sGam = (float*)(smem + OFF_GAMMA);
    float* sBet = (float*)(smem + OFF_BETA);
    const int tid = threadIdx.x, lane = tid & 31, wid = tid >> 5;
    const int q = lane & 3, rq = lane >> 2;
    const int jj = lane >> 3, rr = lane & 7;
    const int belem = ((jj >= 2 ? 8 : 0) + rr) * SW + ((jj & 1) ? 8 : 0);

    sGam[tid] = gamma[tid];
    sBet[tid] = beta[tid];
    load_W_split(smem, Wm, tid);
    __syncthreads();

    float csum[32];
    #pragma unroll
    for (int j = 0; j < 32; j++) csum[j] = 0.f;

    const int NT = (Nrows + 63) >> 6;
    for (int tile = blockIdx.x; tile < NT; tile += gridDim.x){
        const int r0 = tile*64 + wid*16 + rq;
        const bool ok0 = r0 < Nrows, ok1 = (r0 + 8) < Nrows;
        const uint32_t* ph0 = Yhi + (size_t)r0*64;
        const uint32_t* ph1 = ph0 + 8*64;
        const uint32_t* pl0 = Ylo + (size_t)r0*64;
        const uint32_t* pl1 = pl0 + 8*64;

        uint32_t Ahi[32], Alo[32];
        #pragma unroll
        for (int ks = 0; ks < 8; ks++){
            int i0 = ks*8 + q;
            Ahi[ks*4+0] = ok0 ? ph0[i0]     : 0u;
            Ahi[ks*4+1] = ok1 ? ph1[i0]     : 0u;
            Ahi[ks*4+2] = ok0 ? ph0[i0 + 4] : 0u;
            Ahi[ks*4+3] = ok1 ? ph1[i0 + 4] : 0u;
            Alo[ks*4+0] = ok0 ? pl0[i0]     : 0u;
            Alo[ks*4+1] = ok1 ? pl1[i0]     : 0u;
            Alo[ks*4+2] = ok0 ? pl0[i0 + 4] : 0u;
            Alo[ks*4+3] = ok1 ? pl1[i0 + 4] : 0u;
        }

        float acc[16][4];
        #pragma unroll
        for (int t = 0; t < 16; t++)
            #pragma unroll
            for (int j = 0; j < 4; j++) acc[t][j] = 0.f;

        do_pass(acc, Ahi, sb + OFF_WHI, belem);
        do_pass(acc, Ahi, sb + OFF_WLO, belem);
        do_pass(acc, Alo, sb + OFF_WHI, belem);

        float s0=0.f, q0=0.f, s1=0.f, q1=0.f;
        #pragma unroll
        for (int t = 0; t < 16; t++){
            s0 += acc[t][0] + acc[t][1];
            q0 += acc[t][0]*acc[t][0] + acc[t][1]*acc[t][1];
            s1 += acc[t][2] + acc[t][3];
            q1 += acc[t][2]*acc[t][2] + acc[t][3]*acc[t][3];
        }
        #pragma unroll
        for (int o = 1; o <= 2; o <<= 1){
            s0 += __shfl_xor_sync(0xffffffffu, s0, o);
            q0 += __shfl_xor_sync(0xffffffffu, q0, o);
            s1 += __shfl_xor_sync(0xffffffffu, s1, o);
            q1 += __shfl_xor_sync(0xffffffffu, q1, o);
        }
        float mu0 = s0*(1.f/128.f), mu1 = s1*(1.f/128.f);
        float rs0 = rsqrtf(q0*(1.f/128.f) - mu0*mu0 + 1e-5f);
        float rs1 = rsqrtf(q1*(1.f/128.f) - mu1*mu1 + 1e-5f);

        float* px0 = X2 + (size_t)r0*CC + 2*q;
        float* px1 = px0 + 8*CC;
        #pragma unroll
        for (int t = 0; t < 16; t++){
            int c = t*8 + 2*q;
            float g0 = sGam[c], g1 = sGam[c+1], b0 = sBet[c], b1 = sBet[c+1];
            if (ok0){
                float y0 = (acc[t][0]-mu0)*rs0*g0 + b0;
                float y1 = (acc[t][1]-mu0)*rs0*g1 + b1;
                *(float2*)(px0 + t*8) = make_float2(y0, y1);
                csum[t*2]   += y0;
                csum[t*2+1] += y1;
            }
            if (ok1){
                float y0 = (acc[t][2]-mu1)*rs1*g0 + b0;
                float y1 = (acc[t][3]-mu1)*rs1*g1 + b1;
                *(float2*)(px1 + t*8) = make_float2(y0, y1);
                csum[t*2]   += y0;
                csum[t*2+1] += y1;
            }
        }
    }

    #pragma unroll
    for (int j = 0; j < 32; j++){
        float v = csum[j];
        v += __shfl_xor_sync(0xffffffffu, v, 4);
        v += __shfl_xor_sync(0xffffffffu, v, 8);
        v += __shfl_xor_sync(0xffffffffu, v, 16);
        csum[j] = v;
    }
    if (lane < 4){
        #pragma unroll
        for (int t = 0; t < 16; t++){
            atomicAdd(&g_colsum[t*8 + 2*lane],     csum[t*2]);
            atomicAdd(&g_colsum[t*8 + 2*lane + 1], csum[t*2+1]);
        }
    }
}

// ================= zero per-iteration state =================
__global__ void zero_kernel() {
    unsigned i = blockIdx.x * blockDim.x + threadIdx.x;
    unsigned stride = gridDim.x * blockDim.x;
    for (unsigned w = i; w < NWORDS; w += stride){ g_bitmap[w] = 0u; g_dup[w] = 0u; }
    if (i < CC) g_colsum[i] = 0.f;
    if (i == 0) g_ndup = 0u;
}

// ================= SE gate =================
__global__ void se_kernel(const float* __restrict__ w1, const float* __restrict__ b1,
                          const float* __restrict__ w2, const float* __restrict__ b2,
                          float invN)
{
    __shared__ float sq[CC];
    __shared__ float hp[4][32];
    __shared__ float h[32];
    int t = threadIdx.x;
    sq[t] = g_colsum[t] * invN;
    __syncthreads();
    int j = t & 31, grp = t >> 5;
    float a = 0.f;
    #pragma unroll 8
    for (int c = 0; c < 32; c++){
        int cc = grp*32 + c;
        a += sq[cc] * w1[cc*32 + j];
    }
    hp[grp][j] = a;
    __syncthreads();
    if (t < 32){
        float v = b1[t] + hp[0][t] + hp[1][t] + hp[2][t] + hp[3][t];
        h[t] = fmaxf(v, 0.f);
    }
    __syncthreads();
    float o = b2[t];
    #pragma unroll
    for (int jj = 0; jj < 32; jj++) o += h[jj] * w2[jj*CC + t];
    g_scale[t] = 1.f / (1.f + expf(-o));
}

// ================= bitmap + dup detection =================
__global__ void bitmap_kernel(const int* __restrict__ idx, int Nrows) {
    int i = blockIdx.x * blockDim.x + threadIdx.x;
    if (i >= Nrows) return;
    int4 v = ((const int4*)idx)[i];
    unsigned lin = (unsigned)(v.x*STRIDE_Bc + v.y*STRIDE_Tc + v.z*STRIDE_Hc + v.w);
    unsigned bit = 1u << (lin & 31);
    unsigned old = atomicOr(&g_bitmap[lin >> 5], bit);
    if (old & bit){
        unsigned dold = atomicOr(&g_dup[lin >> 5], bit);
        if (!(dold & bit)){
            unsigned pos = atomicAdd(&g_ndup, 1u);
            if (pos < NMAX) g_duplist[pos] = lin;
        }
    }
}

__global__ void scan1_kernel() {
    int b = blockIdx.x, t = threadIdx.x;
    unsigned base = b * 1024;
    unsigned s = 0;
    #pragma unroll
    for (int j = 0; j < 4; j++) s += __popc(g_bitmap[base + t*4 + j]);
    #pragma unroll
    for (int o = 16; o > 0; o >>= 1) s += __shfl_xor_sync(0xffffffffu, s, o);
    __shared__ unsigned ws[8];
    if ((t & 31) == 0) ws[t >> 5] = s;
    __syncthreads();
    if (t == 0) {
        unsigned tot = 0;
        #pragma unroll
        for (int w = 0; w < 8; w++) tot += ws[w];
        g_blocksum[b] = tot;
    }
}

__global__ void scan2_kernel() {
    int t = threadIdx.x, lane = t & 31, w = t >> 5;
    unsigned v = g_blocksum[t];
    unsigned x = v;
    #pragma unroll
    for (int o = 1; o < 32; o <<= 1) {
        unsigned n = __shfl_up_sync(0xffffffffu, x, o);
        if (lane >= o) x += n;
    }
    __shared__ unsigned ws[32];
    if (lane == 31) ws[w] = x;
    __syncthreads();
    if (w == 0) {
        unsigned y = ws[lane];
        #pragma unroll
        for (int o = 1; o < 32; o <<= 1) {
            unsigned n = __shfl_up_sync(0xffffffffu, y, o);
            if (lane >= o) y += n;
        }
        ws[lane] = y;
    }
    __syncthreads();
    unsigned incl = x + (w ? ws[w-1] : 0u);
    g_blockoff[t] = incl - v;
    if (t == 1023) g_U = incl;
}

__global__ void scan3_kernel() {
    int b = blockIdx.x, t = threadIdx.x, lane = t & 31, w = t >> 5;
    unsigned base = b * 1024;
    unsigned wd[4];
    unsigned s = 0;
    #pragma unroll
    for (int j = 0; j < 4; j++) { wd[j] = g_bitmap[base + t*4 + j]; s += __popc(wd[j]); }
    unsigned x = s;
    #pragma unroll
    for (int o = 1; o < 32; o <<= 1) {
        unsigned n = __shfl_up_sync(0xffffffffu, x, o);
        if (lane >= o) x += n;
    }
    __shared__ unsigned ws[8];
    if (lane == 31) ws[w] = x;
    __syncthreads();
    if (t == 0) {
        unsigned acc = 0;
        #pragma unroll
        for (int i = 0; i < 8; i++) { unsigned tmp = ws[i]; ws[i] = acc; acc += tmp; }
    }
    __syncthreads();
    unsigned run = ws[w] + (x - s) + g_blockoff[b];
    #pragma unroll
    for (int j = 0; j < 4; j++) {
        g_wordscan[base + t*4 + j] = run;
        run += __popc(wd[j]);
    }
}

__device__ __forceinline__ unsigned rank_of(unsigned lin){
    unsigned wo = lin >> 5, bit = lin & 31;
    return g_wordscan[wo] + __popc(g_bitmap[wo] & ((1u << bit) - 1u));
}

// ================= zero dup rows (before scatter) =================
__global__ void zerodup_kernel(float* __restrict__ outM){
    int w = (blockIdx.x * blockDim.x + threadIdx.x) >> 5;
    int lane = threadIdx.x & 31;
    unsigned nd = g_ndup; if (nd > NMAX) nd = NMAX;
    int tot = gridDim.x * (blockDim.x >> 5);
    for (unsigned i = w; i < nd; i += tot){
        unsigned r = rank_of(g_duplist[i]);
        ((float4*)(outM + (size_t)r*CC))[lane] = make_float4(0.f,0.f,0.f,0.f);
    }
}

// ================= scatter: fused relu/valid for non-dup rows =================
__global__ void scatter_kernel(const float* __restrict__ feats, const int* __restrict__ idx,
                               float* __restrict__ outM, float* __restrict__ outIdx,
                               float* __restrict__ outValid,
                               int hasIdx, int hasValid, int Nrows)
{
    int lane = threadIdx.x & 31, w = threadIdx.x >> 5;
    int row = blockIdx.x * 8 + w;
    if (row >= Nrows) return;
    int4 iv = ((const int4*)idx)[row];
    unsigned lin = (unsigned)(iv.x*STRIDE_Bc + iv.y*STRIDE_Tc + iv.z*STRIDE_Hc + iv.w);
    unsigned wo = lin >> 5, bit = lin & 31;
    unsigned r = g_wordscan[wo] + __popc(g_bitmap[wo] & ((1u << bit) - 1u));
    bool isdup = (g_dup[wo] >> bit) & 1u;

    float4 v  = ((const float4*)g_X2)[(size_t)row*32 + lane];
    float4 f  = ((const float4*)feats)[(size_t)row*32 + lane];
    float4 sc = ((const float4*)g_scale)[lane];
    float4 o;
    o.x = v.x*sc.x + f.x;
    o.y = v.y*sc.y + f.y;
    o.z = v.z*sc.z + f.z;
    o.w = v.w*sc.w + f.w;

    if (!isdup){
        float s = fabsf(o.x) + fabsf(o.y) + fabsf(o.z) + fabsf(o.w);
        #pragma unroll
        for (int off = 16; off > 0; off >>= 1) s += __shfl_xor_sync(0xffffffffu, s, off);
        bool valid = (s > 1e-8f);
        float4 ov;
        if (valid){
            ov.x = fmaxf(o.x, 0.f); ov.y = fmaxf(o.y, 0.f);
            ov.z = fmaxf(o.z, 0.f); ov.w = fmaxf(o.w, 0.f);
        } else {
            ov = make_float4(0.f,0.f,0.f,0.f);
        }
        ((float4*)(outM + (size_t)r*CC))[lane] = ov;
        if (lane == 0 && hasValid) outValid[r] = valid ? 1.f : 0.f;
    } else {
        float* dst = &outM[(size_t)r*CC + lane*4];
        atomicAdd(dst+0, o.x); atomicAdd(dst+1, o.y);
        atomicAdd(dst+2, o.z); atomicAdd(dst+3, o.w);
    }
    if (hasIdx && lane == 0)
        ((float4*)outIdx)[r] = make_float4((float)iv.x, (float)iv.y, (float)iv.z, (float)iv.w);
}

// ================= finalize dup rows (relu + valid) =================
__global__ void finalizedup_kernel(float* __restrict__ outM, float* __restrict__ outValid,
                                   int hasValid){
    int w = (blockIdx.x * blockDim.x + threadIdx.x) >> 5;
    int lane = threadIdx.x & 31;
    unsigned nd = g_ndup; if (nd > NMAX) nd = NMAX;
    int tot = gridDim.x * (blockDim.x >> 5);
    for (unsigned i = w; i < nd; i += tot){
        unsigned r = rank_of(g_duplist[i]);
        float4* p = (float4*)(outM + (size_t)r*CC) + lane;
        float4 v = *p;
        float s = fabsf(v.x) + fabsf(v.y) + fabsf(v.z) + fabsf(v.w);
        #pragma unroll
        for (int off = 16; off > 0; off >>= 1) s += __shfl_xor_sync(0xffffffffu, s, off);
        bool valid = (s > 1e-8f);
        float4 ov;
        if (valid){
            ov.x = fmaxf(v.x, 0.f); ov.y = fmaxf(v.y, 0.f);
            ov.z = fmaxf(v.z, 0.f); ov.w = fmaxf(v.w, 0.f);
        } else {
            ov = make_float4(0.f,0.f,0.f,0.f);
        }
        *p = ov;
        if (lane == 0 && hasValid) outValid[r] = valid ? 1.f : 0.f;
    }
}

// ================= tail: rows >= U =================
__global__ void tail_kernel(float* __restrict__ outM, float* __restrict__ outIdx,
                            float* __restrict__ outValid,
                            int hasIdx, int hasValid, int Mrows)
{
    int lane = threadIdx.x & 31, w = threadIdx.x >> 5;
    int row = blockIdx.x * 8 + w;
    unsigned U = g_U;
    if (row >= Mrows || (unsigned)row < U) return;
    ((float4*)(outM + (size_t)row*CC))[lane] = make_float4(0.f,0.f,0.f,0.f);
    if (lane == 0){
        if (hasValid) outValid[row] = 0.f;
        if (hasIdx) ((float4*)outIdx)[row] = make_float4(8.f, 0.f, 0.f, 0.f);
    }
}

// ================= launch =================
extern "C" void kernel_launch(void* const* d_in, const int* in_sizes, int n_in,
                              void* d_out, int out_size)
{
    const float* feats = (const float*)d_in[0];
    const int*   indices = (const int*)d_in[1];
    const float* W1   = (const float*)d_in[2];
    const float* ln1g = (const float*)d_in[3];
    const float* ln1b = (const float*)d_in[4];
    const float* W2   = (const float*)d_in[5];
    const float* ln2g = (const float*)d_in[6];
    const float* ln2b = (const float*)d_in[7];
    const float* sew1 = (const float*)d_in[8];
    const float* seb1 = (const float*)d_in[9];
    const float* sew2 = (const float*)d_in[10];
    const float* seb2 = (const float*)d_in[11];

    int Nr = in_sizes[0] / CC;
    int M  = 2 * Nr;

    float* outM = (float*)d_out;
    long long osz = (long long)out_size;
    int hasIdx   = osz >= (long long)M * (CC + 4);
    int hasValid = osz >= (long long)M * (CC + 5);
    float* outIdx   = outM + (size_t)M * CC;
    float* outValid = outIdx + (hasIdx ? (size_t)M * 4 : 0);

    void *pyh = nullptr, *pyl = nullptr, *px2 = nullptr;
    cudaGetSymbolAddress(&pyh, g_Y1hi);
    cudaGetSymbolAddress(&pyl, g_Y1lo);
    cudaGetSymbolAddress(&px2, g_X2);

    cudaFuncSetAttribute(gemm1_kernel, cudaFuncAttributeMaxDynamicSharedMemorySize, SMEM_GEMM);
    cudaFuncSetAttribute(gemm2_kernel, cudaFuncAttributeMaxDynamicSharedMemorySize, SMEM_GEMM);

    // fallback only if layout is unexpected (then scatter coverage assumptions differ)
    if (!(hasIdx && hasValid))
        cudaMemsetAsync(d_out, 0, (size_t)out_size * sizeof(float));

    zero_kernel<<<2048, 256>>>();

    gemm1_kernel<<<444, 128, SMEM_GEMM>>>(feats, W1, ln1g, ln1b,
                                          (uint32_t*)pyh, (uint32_t*)pyl, Nr);
    gemm2_kernel<<<444, 128, SMEM_GEMM>>>((const uint32_t*)pyh, (const uint32_t*)pyl,
                                          W2, ln2g, ln2b, (float*)px2, Nr);
    se_kernel<<<1, CC>>>(sew1, seb1, sew2, seb2, 1.0f / (float)Nr);

    bitmap_kernel<<<(Nr + 255) / 256, 256>>>(indices, Nr);
    scan1_kernel<<<1024, 256>>>();
    scan2_kernel<<<1, 1024>>>();
    scan3_kernel<<<1024, 256>>>();

    zerodup_kernel<<<256, 256>>>(outM);
    scatter_kernel<<<(Nr + 7) / 8, 256>>>(feats, indices, outM, outIdx, outValid,
                                          hasIdx, hasValid, Nr);
    finalizedup_kernel<<<256, 256>>>(outM, outValid, hasValid);
    tail_kernel<<<(M + 7) / 8, 256>>>(outM, outIdx, outValid, hasIdx, hasValid, M);
}

// round 5
// speedup vs baseline: 1.7913x; 1.0752x over previous
#include <cuda_runtime.h>
#include <cuda_bf16.h>
#include <math.h>
#include <stdint.h>

#define CC 128
#define NMAX 300000
#define NWORDS (1u<<20)
#define STRIDE_Bc 4194304
#define STRIDE_Tc 262144
#define STRIDE_Hc 512

// ================= device scratch =================
__device__ uint32_t g_Y1hi[(size_t)NMAX*64];   // bf16x2 packed, [row][64]
__device__ uint32_t g_Y1lo[(size_t)NMAX*64];
__device__ float    g_X2[(size_t)NMAX*CC];
__device__ unsigned g_bitmap[NWORDS];
__device__ unsigned g_dup[NWORDS];
__device__ unsigned g_wordscan[NWORDS];
__device__ unsigned g_blocksum[1024];
__device__ unsigned g_blockoff[1024];
__device__ unsigned g_U;
__device__ unsigned g_ndup;
__device__ unsigned g_duplist[NMAX];
__device__ float    g_colsum[CC];
__device__ float    g_scale[CC];

// ================= helpers =================
__device__ __forceinline__ uint32_t smem_u32(const void* p){
    uint32_t a;
    asm("{ .reg .u64 t; cvta.to.shared.u64 t, %1; cvt.u32.u64 %0, t; }" : "=r"(a) : "l"(p));
    return a;
}

__device__ __forceinline__ void ldsm_x4(uint32_t addr, uint32_t& r0, uint32_t& r1,
                                        uint32_t& r2, uint32_t& r3){
    asm volatile("ldmatrix.sync.aligned.m8n8.x4.shared.b16 {%0,%1,%2,%3}, [%4];"
        : "=r"(r0),"=r"(r1),"=r"(r2),"=r"(r3) : "r"(addr));
}

__device__ __forceinline__ void mma_bf16(float* d, const uint32_t* a, uint32_t b0, uint32_t b1){
    asm volatile("mma.sync.aligned.m16n8k16.row.col.f32.bf16.bf16.f32 "
        "{%0,%1,%2,%3}, {%4,%5,%6,%7}, {%8,%9}, {%0,%1,%2,%3};"
        : "+f"(d[0]),"+f"(d[1]),"+f"(d[2]),"+f"(d[3])
        : "r"(a[0]),"r"(a[1]),"r"(a[2]),"r"(a[3]), "r"(b0),"r"(b1));
}

__device__ __forceinline__ void split2(float a, float b, uint32_t& hi, uint32_t& lo){
    __nv_bfloat162 h = __floats2bfloat162_rn(a, b);
    hi = *reinterpret_cast<uint32_t*>(&h);
    float ra = a - __bfloat162float(h.x);
    float rb = b - __bfloat162float(h.y);
    __nv_bfloat162 l = __floats2bfloat162_rn(ra, rb);
    lo = *reinterpret_cast<uint32_t*>(&l);
}

// SMEM layout for GEMM kernels
#define SW        136
#define OFF_GAMMA 0
#define OFF_BETA  512
#define OFF_WHI   1024
#define OFF_WLO   (1024 + 128*SW*2)
#define SMEM_GEMM (OFF_WLO + 128*SW*2)

__device__ __forceinline__ void load_W_split(char* smem, const float* __restrict__ Wm, int tid){
    __nv_bfloat16* sWhi = (__nv_bfloat16*)(smem + OFF_WHI);
    __nv_bfloat16* sWlo = (__nv_bfloat16*)(smem + OFF_WLO);
    #pragma unroll 4
    for (int k = 0; k < CC; k++){
        float w = Wm[k*CC + tid];
        __nv_bfloat16 h = __float2bfloat16(w);
        float r = w - __bfloat162float(h);
        sWhi[tid*SW + k] = h;
        sWlo[tid*SW + k] = __float2bfloat16(r);
    }
}

__device__ __forceinline__ void do_pass(float (&acc)[16][4], const uint32_t (&Ar)[32],
                                        uint32_t wb, int belem){
    #pragma unroll
    for (int np = 0; np < 8; np++){
        #pragma unroll
        for (int ks = 0; ks < 8; ks++){
            uint32_t addr = wb + (uint32_t)((np*16*SW + ks*16 + belem) * 2);
            uint32_t b0,b1,b2,b3;
            ldsm_x4(addr, b0, b1, b2, b3);
            mma_bf16(acc[np*2],   Ar + ks*4, b0, b1);
            mma_bf16(acc[np*2+1], Ar + ks*4, b2, b3);
        }
    }
}

// ================= GEMM1 (pipelined A fetch) =================
__global__ __launch_bounds__(128, 2)
void gemm1_kernel(const float* __restrict__ A, const float* __restrict__ Wm,
                  const float* __restrict__ gamma, const float* __restrict__ beta,
                  uint32_t* __restrict__ Yhi, uint32_t* __restrict__ Ylo, int Nrows)
{
    extern __shared__ char smem[];
    uint32_t sb = smem_u32(smem);
    float* sGam = (float*)(smem + OFF_GAMMA);
    float* sBet = (float*)(smem + OFF_BETA);
    const int tid = threadIdx.x, lane = tid & 31, wid = tid >> 5;
    const int q = lane & 3, rq = lane >> 2;
    const int jj = lane >> 3, rr = lane & 7;
    const int belem = ((jj >= 2 ? 8 : 0) + rr) * SW + ((jj & 1) ? 8 : 0);

    sGam[tid] = gamma[tid];
    sBet[tid] = beta[tid];
    load_W_split(smem, Wm, tid);
    __syncthreads();

    const int NT = (Nrows + 63) >> 6;
    const int G = gridDim.x;

    float2 raw[32];
    const float2 z2 = make_float2(0.f, 0.f);

    // prologue load for first owned tile
    int tile0 = blockIdx.x;
    if (tile0 < NT){
        int r = tile0*64 + wid*16 + rq;
        bool o0 = r < Nrows, o1 = (r + 8) < Nrows;
        const float* p0 = A + (size_t)r * CC;
        const float* p1 = p0 + 8 * CC;
        #pragma unroll
        for (int ks = 0; ks < 8; ks++){
            int k0 = ks*16 + 2*q;
            raw[ks*4+0] = o0 ? *(const float2*)(p0 + k0)     : z2;
            raw[ks*4+1] = o1 ? *(const float2*)(p1 + k0)     : z2;
            raw[ks*4+2] = o0 ? *(const float2*)(p0 + k0 + 8) : z2;
            raw[ks*4+3] = o1 ? *(const float2*)(p1 + k0 + 8) : z2;
        }
    }

    for (int tile = tile0; tile < NT; tile += G){
        const int r0 = tile*64 + wid*16 + rq;
        const bool ok0 = r0 < Nrows, ok1 = (r0 + 8) < Nrows;

        // split raw -> fragments (frees raw for the prefetch)
        uint32_t Ahi[32], Alo[32];
        #pragma unroll
        for (int i = 0; i < 32; i++)
            split2(raw[i].x, raw[i].y, Ahi[i], Alo[i]);

        // prefetch next tile's raw A (in flight during MMA passes)
        int tnext = tile + G;
        if (tnext < NT){
            int r = tnext*64 + wid*16 + rq;
            bool o0 = r < Nrows, o1 = (r + 8) < Nrows;
            const float* p0 = A + (size_t)r * CC;
            const float* p1 = p0 + 8 * CC;
            #pragma unroll
            for (int ks = 0; ks < 8; ks++){
                int k0 = ks*16 + 2*q;
                raw[ks*4+0] = o0 ? *(const float2*)(p0 + k0)     : z2;
                raw[ks*4+1] = o1 ? *(const float2*)(p1 + k0)     : z2;
                raw[ks*4+2] = o0 ? *(const float2*)(p0 + k0 + 8) : z2;
                raw[ks*4+3] = o1 ? *(const float2*)(p1 + k0 + 8) : z2;
            }
        }

        float acc[16][4];
        #pragma unroll
        for (int t = 0; t < 16; t++)
            #pragma unroll
            for (int j = 0; j < 4; j++) acc[t][j] = 0.f;

        do_pass(acc, Ahi, sb + OFF_WHI, belem);
        do_pass(acc, Ahi, sb + OFF_WLO, belem);
        do_pass(acc, Alo, sb + OFF_WHI, belem);

        float s0=0.f, q0=0.f, s1=0.f, q1=0.f;
        #pragma unroll
        for (int t = 0; t < 16; t++){
            s0 += acc[t][0] + acc[t][1];
            q0 += acc[t][0]*acc[t][0] + acc[t][1]*acc[t][1];
            s1 += acc[t][2] + acc[t][3];
            q1 += acc[t][2]*acc[t][2] + acc[t][3]*acc[t][3];
        }
        #pragma unroll
        for (int o = 1; o <= 2; o <<= 1){
            s0 += __shfl_xor_sync(0xffffffffu, s0, o);
            q0 += __shfl_xor_sync(0xffffffffu, q0, o);
            s1 += __shfl_xor_sync(0xffffffffu, s1, o);
            q1 += __shfl_xor_sync(0xffffffffu, q1, o);
        }
        float mu0 = s0*(1.f/128.f), mu1 = s1*(1.f/128.f);
        float rs0 = rsqrtf(q0*(1.f/128.f) - mu0*mu0 + 1e-5f);
        float rs1 = rsqrtf(q1*(1.f/128.f) - mu1*mu1 + 1e-5f);

        uint32_t* yh0 = Yhi + (size_t)r0*64 + q;
        uint32_t* yl0 = Ylo + (size_t)r0*64 + q;
        uint32_t* yh1 = yh0 + 8*64;
        uint32_t* yl1 = yl0 + 8*64;
        #pragma unroll
        for (int t = 0; t < 16; t++){
            int c = t*8 + 2*q;
            float g0 = sGam[c], g1 = sGam[c+1], b0 = sBet[c], b1 = sBet[c+1];
            if (ok0){
                float y0 = fmaxf((acc[t][0]-mu0)*rs0*g0 + b0, 0.f);
                float y1 = fmaxf((acc[t][1]-mu0)*rs0*g1 + b1, 0.f);
                uint32_t h, l; split2(y0, y1, h, l);
                yh0[t*4] = h; yl0[t*4] = l;
            }
            if (ok1){
                float y0 = fmaxf((acc[t][2]-mu1)*rs1*g0 + b0, 0.f);
                float y1 = fmaxf((acc[t][3]-mu1)*rs1*g1 + b1, 0.f);
                uint32_t h, l; split2(y0, y1, h, l);
                yh1[t*4] = h; yl1[t*4] = l;
            }
        }
    }
}

// ================= GEMM2 (pipelined A fetch) =================
__global__ __launch_bounds__(128, 2)
void gemm2_kernel(const uint32_t* __restrict__ Yhi, const uint32_t* __restrict__ Ylo,
                  const float* __restrict__ Wm,
                  const float* __restrict__ gamma, const float* __restrict__ beta,
                  float* __restrict__ X2, int Nrows)
{
    extern __shared__ char smem[];
    uint32_t sb = smem_u32(smem);
    float* sGam = (float*)(smem + OFF_GAMMA);
    float* sBet = (float*)(smem + OFF_BETA);
    const int tid = threadIdx.x, lane = tid & 31, wid = tid >> 5;
    const int q = lane & 3, rq = lane >> 2;
    const int jj = lane >> 3, rr = lane & 7;
    const int belem = ((jj >= 2 ? 8 : 0) + rr) * SW + ((jj & 1) ? 8 : 0);

    sGam[tid] = gamma[tid];
    sBet[tid] = beta[tid];
    load_W_split(smem, Wm, tid);
    __syncthreads();

    float csum[32];
    #pragma unroll
    for (int j = 0; j < 32; j++) csum[j] = 0.f;

    const int NT = (Nrows + 63) >> 6;
    const int G = gridDim.x;

    uint32_t Ahi[32], Alo[32];

    int tile0 = blockIdx.x;
    if (tile0 < NT){
        int r = tile0*64 + wid*16 + rq;
        bool o0 = r < Nrows, o1 = (r + 8) < Nrows;
        const uint32_t* ph0 = Yhi + (size_t)r*64;
        const uint32_t* ph1 = ph0 + 8*64;
        const uint32_t* pl0 = Ylo + (size_t)r*64;
        const uint32_t* pl1 = pl0 + 8*64;
        #pragma unroll
        for (int ks = 0; ks < 8; ks++){
            int i0 = ks*8 + q;
            Ahi[ks*4+0] = o0 ? ph0[i0]     : 0u;
            Ahi[ks*4+1] = o1 ? ph1[i0]     : 0u;
            Ahi[ks*4+2] = o0 ? ph0[i0 + 4] : 0u;
            Ahi[ks*4+3] = o1 ? ph1[i0 + 4] : 0u;
            Alo[ks*4+0] = o0 ? pl0[i0]     : 0u;
            Alo[ks*4+1] = o1 ? pl1[i0]     : 0u;
            Alo[ks*4+2] = o0 ? pl0[i0 + 4] : 0u;
            Alo[ks*4+3] = o1 ? pl1[i0 + 4] : 0u;
        }
    }

    for (int tile = tile0; tile < NT; tile += G){
        const int r0 = tile*64 + wid*16 + rq;
        const bool ok0 = r0 < Nrows, ok1 = (r0 + 8) < Nrows;

        // current fragments (copy so prefetch can reuse Ahi/Alo)
        uint32_t Chi[32], Clo[32];
        #pragma unroll
        for (int i = 0; i < 32; i++){ Chi[i] = Ahi[i]; Clo[i] = Alo[i]; }

        int tnext = tile + G;
        if (tnext < NT){
            int r = tnext*64 + wid*16 + rq;
            bool o0 = r < Nrows, o1 = (r + 8) < Nrows;
            const uint32_t* ph0 = Yhi + (size_t)r*64;
            const uint32_t* ph1 = ph0 + 8*64;
            const uint32_t* pl0 = Ylo + (size_t)r*64;
            const uint32_t* pl1 = pl0 + 8*64;
            #pragma unroll
            for (int ks = 0; ks < 8; ks++){
                int i0 = ks*8 + q;
                Ahi[ks*4+0] = o0 ? ph0[i0]     : 0u;
                Ahi[ks*4+1] = o1 ? ph1[i0]     : 0u;
                Ahi[ks*4+2] = o0 ? ph0[i0 + 4] : 0u;
                Ahi[ks*4+3] = o1 ? ph1[i0 + 4] : 0u;
                Alo[ks*4+0] = o0 ? pl0[i0]     : 0u;
                Alo[ks*4+1] = o1 ? pl1[i0]     : 0u;
                Alo[ks*4+2] = o0 ? pl0[i0 + 4] : 0u;
                Alo[ks*4+3] = o1 ? pl1[i0 + 4] : 0u;
            }
        }

        float acc[16][4];
        #pragma unroll
        for (int t = 0; t < 16; t++)
            #pragma unroll
            for (int j = 0; j < 4; j++) acc[t][j] = 0.f;

        do_pass(acc, Chi, sb + OFF_WHI, belem);
        do_pass(acc, Chi, sb + OFF_WLO, belem);
        do_pass(acc, Clo, sb + OFF_WHI, belem);

        float s0=0.f, q0=0.f, s1=0.f, q1=0.f;
        #pragma unroll
        for (int t = 0; t < 16; t++){
            s0 += acc[t][0] + acc[t][1];
            q0 += acc[t][0]*acc[t][0] + acc[t][1]*acc[t][1];
            s1 += acc[t][2] + acc[t][3];
            q1 += acc[t][2]*acc[t][2] + acc[t][3]*acc[t][3];
        }
        #pragma unroll
        for (int o = 1; o <= 2; o <<= 1){
            s0 += __shfl_xor_sync(0xffffffffu, s0, o);
            q0 += __shfl_xor_sync(0xffffffffu, q0, o);
            s1 += __shfl_xor_sync(0xffffffffu, s1, o);
            q1 += __shfl_xor_sync(0xffffffffu, q1, o);
        }
        float mu0 = s0*(1.f/128.f), mu1 = s1*(1.f/128.f);
        float rs0 = rsqrtf(q0*(1.f/128.f) - mu0*mu0 + 1e-5f);
        float rs1 = rsqrtf(q1*(1.f/128.f) - mu1*mu1 + 1e-5f);

        float* px0 = X2 + (size_t)r0*CC + 2*q;
        float* px1 = px0 + 8*CC;
        #pragma unroll
        for (int t = 0; t < 16; t++){
            int c = t*8 + 2*q;
            float g0 = sGam[c], g1 = sGam[c+1], b0 = sBet[c], b1 = sBet[c+1];
            if (ok0){
                float y0 = (acc[t][0]-mu0)*rs0*g0 + b0;
                float y1 = (acc[t][1]-mu0)*rs0*g1 + b1;
                *(float2*)(px0 + t*8) = make_float2(y0, y1);
                csum[t*2]   += y0;
                csum[t*2+1] += y1;
            }
            if (ok1){
                float y0 = (acc[t][2]-mu1)*rs1*g0 + b0;
                float y1 = (acc[t][3]-mu1)*rs1*g1 + b1;
                *(float2*)(px1 + t*8) = make_float2(y0, y1);
                csum[t*2]   += y0;
                csum[t*2+1] += y1;
            }
        }
    }

    #pragma unroll
    for (int j = 0; j < 32; j++){
        float v = csum[j];
        v += __shfl_xor_sync(0xffffffffu, v, 4);
        v += __shfl_xor_sync(0xffffffffu, v, 8);
        v += __shfl_xor_sync(0xffffffffu, v, 16);
        csum[j] = v;
    }
    if (lane < 4){
        #pragma unroll
        for (int t = 0; t < 16; t++){
            atomicAdd(&g_colsum[t*8 + 2*lane],     csum[t*2]);
            atomicAdd(&g_colsum[t*8 + 2*lane + 1], csum[t*2+1]);
        }
    }
}

// ================= zero per-iteration state =================
__global__ void zero_kernel() {
    unsigned i = blockIdx.x * blockDim.x + threadIdx.x;
    unsigned stride = gridDim.x * blockDim.x;
    for (unsigned w = i; w < NWORDS; w += stride){ g_bitmap[w] = 0u; g_dup[w] = 0u; }
    if (i < CC) g_colsum[i] = 0.f;
    if (i == 0) g_ndup = 0u;
}

// ================= SE gate =================
__global__ void se_kernel(const float* __restrict__ w1, const float* __restrict__ b1,
                          const float* __restrict__ w2, const float* __restrict__ b2,
                          float invN)
{
    __shared__ float sq[CC];
    __shared__ float hp[4][32];
    __shared__ float h[32];
    int t = threadIdx.x;
    sq[t] = g_colsum[t] * invN;
    __syncthreads();
    int j = t & 31, grp = t >> 5;
    float a = 0.f;
    #pragma unroll 8
    for (int c = 0; c < 32; c++){
        int cc = grp*32 + c;
        a += sq[cc] * w1[cc*32 + j];
    }
    hp[grp][j] = a;
    __syncthreads();
    if (t < 32){
        float v = b1[t] + hp[0][t] + hp[1][t] + hp[2][t] + hp[3][t];
        h[t] = fmaxf(v, 0.f);
    }
    __syncthreads();
    float o = b2[t];
    #pragma unroll
    for (int jj = 0; jj < 32; jj++) o += h[jj] * w2[jj*CC + t];
    g_scale[t] = 1.f / (1.f + expf(-o));
}

// ================= bitmap + dup detection =================
__global__ void bitmap_kernel(const int* __restrict__ idx, int Nrows) {
    int i = blockIdx.x * blockDim.x + threadIdx.x;
    if (i >= Nrows) return;
    int4 v = ((const int4*)idx)[i];
    unsigned lin = (unsigned)(v.x*STRIDE_Bc + v.y*STRIDE_Tc + v.z*STRIDE_Hc + v.w);
    unsigned bit = 1u << (lin & 31);
    unsigned old = atomicOr(&g_bitmap[lin >> 5], bit);
    if (old & bit){
        unsigned dold = atomicOr(&g_dup[lin >> 5], bit);
        if (!(dold & bit)){
            unsigned pos = atomicAdd(&g_ndup, 1u);
            if (pos < NMAX) g_duplist[pos] = lin;
        }
    }
}

__global__ void scan1_kernel() {
    int b = blockIdx.x, t = threadIdx.x;
    unsigned base = b * 1024;
    unsigned s = 0;
    #pragma unroll
    for (int j = 0; j < 4; j++) s += __popc(g_bitmap[base + t*4 + j]);
    #pragma unroll
    for (int o = 16; o > 0; o >>= 1) s += __shfl_xor_sync(0xffffffffu, s, o);
    __shared__ unsigned ws[8];
    if ((t & 31) == 0) ws[t >> 5] = s;
    __syncthreads();
    if (t == 0) {
        unsigned tot = 0;
        #pragma unroll
        for (int w = 0; w < 8; w++) tot += ws[w];
        g_blocksum[b] = tot;
    }
}

__global__ void scan2_kernel() {
    int t = threadIdx.x, lane = t & 31, w = t >> 5;
    unsigned v = g_blocksum[t];
    unsigned x = v;
    #pragma unroll
    for (int o = 1; o < 32; o <<= 1) {
        unsigned n = __shfl_up_sync(0xffffffffu, x, o);
        if (lane >= o) x += n;
    }
    __shared__ unsigned ws[32];
    if (lane == 31) ws[w] = x;
    __syncthreads();
    if (w == 0) {
        unsigned y = ws[lane];
        #pragma unroll
        for (int o = 1; o < 32; o <<= 1) {
            unsigned n = __shfl_up_sync(0xffffffffu, y, o);
            if (lane >= o) y += n;
        }
        ws[lane] = y;
    }
    __syncthreads();
    unsigned incl = x + (w ? ws[w-1] : 0u);
    g_blockoff[t] = incl - v;
    if (t == 1023) g_U = incl;
}

__global__ void scan3_kernel() {
    int b = blockIdx.x, t = threadIdx.x, lane = t & 31, w = t >> 5;
    unsigned base = b * 1024;
    unsigned wd[4];
    unsigned s = 0;
    #pragma unroll
    for (int j = 0; j < 4; j++) { wd[j] = g_bitmap[base + t*4 + j]; s += __popc(wd[j]); }
    unsigned x = s;
    #pragma unroll
    for (int o = 1; o < 32; o <<= 1) {
        unsigned n = __shfl_up_sync(0xffffffffu, x, o);
        if (lane >= o) x += n;
    }
    __shared__ unsigned ws[8];
    if (lane == 31) ws[w] = x;
    __syncthreads();
    if (t == 0) {
        unsigned acc = 0;
        #pragma unroll
        for (int i = 0; i < 8; i++) { unsigned tmp = ws[i]; ws[i] = acc; acc += tmp; }
    }
    __syncthreads();
    unsigned run = ws[w] + (x - s) + g_blockoff[b];
    #pragma unroll
    for (int j = 0; j < 4; j++) {
        g_wordscan[base + t*4 + j] = run;
        run += __popc(wd[j]);
    }
}

__device__ __forceinline__ unsigned rank_of(unsigned lin){
    unsigned wo = lin >> 5, bit = lin & 31;
    return g_wordscan[wo] + __popc(g_bitmap[wo] & ((1u << bit) - 1u));
}

// ================= zero dup rows (before scatter) =================
__global__ void zerodup_kernel(float* __restrict__ outM){
    int w = (blockIdx.x * blockDim.x + threadIdx.x) >> 5;
    int lane = threadIdx.x & 31;
    unsigned nd = g_ndup; if (nd > NMAX) nd = NMAX;
    int tot = gridDim.x * (blockDim.x >> 5);
    for (unsigned i = w; i < nd; i += tot){
        unsigned r = rank_of(g_duplist[i]);
        ((float4*)(outM + (size_t)r*CC))[lane] = make_float4(0.f,0.f,0.f,0.f);
    }
}

// ================= scatter: fused relu/valid for non-dup rows =================
__global__ void scatter_kernel(const float* __restrict__ feats, const int* __restrict__ idx,
                               float* __restrict__ outM, float* __restrict__ outIdx,
                               float* __restrict__ outValid,
                               int hasIdx, int hasValid, int Nrows)
{
    int lane = threadIdx.x & 31, w = threadIdx.x >> 5;
    int row = blockIdx.x * 8 + w;
    if (row >= Nrows) return;
    int4 iv = ((const int4*)idx)[row];
    unsigned lin = (unsigned)(iv.x*STRIDE_Bc + iv.y*STRIDE_Tc + iv.z*STRIDE_Hc + iv.w);
    unsigned wo = lin >> 5, bit = lin & 31;
    unsigned r = g_wordscan[wo] + __popc(g_bitmap[wo] & ((1u << bit) - 1u));
    bool isdup = (g_dup[wo] >> bit) & 1u;

    float4 v  = ((const float4*)g_X2)[(size_t)row*32 + lane];
    float4 f  = ((const float4*)feats)[(size_t)row*32 + lane];
    float4 sc = ((const float4*)g_scale)[lane];
    float4 o;
    o.x = v.x*sc.x + f.x;
    o.y = v.y*sc.y + f.y;
    o.z = v.z*sc.z + f.z;
    o.w = v.w*sc.w + f.w;

    if (!isdup){
        float s = fabsf(o.x) + fabsf(o.y) + fabsf(o.z) + fabsf(o.w);
        #pragma unroll
        for (int off = 16; off > 0; off >>= 1) s += __shfl_xor_sync(0xffffffffu, s, off);
        bool valid = (s > 1e-8f);
        float4 ov;
        if (valid){
            ov.x = fmaxf(o.x, 0.f); ov.y = fmaxf(o.y, 0.f);
            ov.z = fmaxf(o.z, 0.f); ov.w = fmaxf(o.w, 0.f);
        } else {
            ov = make_float4(0.f,0.f,0.f,0.f);
        }
        ((float4*)(outM + (size_t)r*CC))[lane] = ov;
        if (lane == 0 && hasValid) outValid[r] = valid ? 1.f : 0.f;
    } else {
        float* dst = &outM[(size_t)r*CC + lane*4];
        atomicAdd(dst+0, o.x); atomicAdd(dst+1, o.y);
        atomicAdd(dst+2, o.z); atomicAdd(dst+3, o.w);
    }
    if (hasIdx && lane == 0)
        ((float4*)outIdx)[r] = make_float4((float)iv.x, (float)iv.y, (float)iv.z, (float)iv.w);
}

// ================= finalize dup rows (relu + valid) =================
__global__ void finalizedup_kernel(float* __restrict__ outM, float* __restrict__ outValid,
                                   int hasValid){
    int w = (blockIdx.x * blockDim.x + threadIdx.x) >> 5;
    int lane = threadIdx.x & 31;
    unsigned nd = g_ndup; if (nd > NMAX) nd = NMAX;
    int tot = gridDim.x * (blockDim.x >> 5);
    for (unsigned i = w; i < nd; i += tot){
        unsigned r = rank_of(g_duplist[i]);
        float4* p = (float4*)(outM + (size_t)r*CC) + lane;
        float4 v = *p;
        float s = fabsf(v.x) + fabsf(v.y) + fabsf(v.z) + fabsf(v.w);
        #pragma unroll
        for (int off = 16; off > 0; off >>= 1) s += __shfl_xor_sync(0xffffffffu, s, off);
        bool valid = (s > 1e-8f);
        float4 ov;
        if (valid){
            ov.x = fmaxf(v.x, 0.f); ov.y = fmaxf(v.y, 0.f);
            ov.z = fmaxf(v.z, 0.f); ov.w = fmaxf(v.w, 0.f);
        } else {
            ov = make_float4(0.f,0.f,0.f,0.f);
        }
        *p = ov;
        if (lane == 0 && hasValid) outValid[r] = valid ? 1.f : 0.f;
    }
}

// ================= tail: rows >= U =================
__global__ void tail_kernel(float* __restrict__ outM, float* __restrict__ outIdx,
                            float* __restrict__ outValid,
                            int hasIdx, int hasValid, int Mrows)
{
    int lane = threadIdx.x & 31, w = threadIdx.x >> 5;
    int row = blockIdx.x * 8 + w;
    unsigned U = g_U;
    if (row >= Mrows || (unsigned)row < U) return;
    ((float4*)(outM + (size_t)row*CC))[lane] = make_float4(0.f,0.f,0.f,0.f);
    if (lane == 0){
        if (hasValid) outValid[row] = 0.f;
        if (hasIdx) ((float4*)outIdx)[row] = make_float4(8.f, 0.f, 0.f, 0.f);
    }
}

// ================= launch =================
extern "C" void kernel_launch(void* const* d_in, const int* in_sizes, int n_in,
                              void* d_out, int out_size)
{
    const float* feats = (const float*)d_in[0];
    const int*   indices = (const int*)d_in[1];
    const float* W1   = (const float*)d_in[2];
    const float* ln1g = (const float*)d_in[3];
    const float* ln1b = (const float*)d_in[4];
    const float* W2   = (const float*)d_in[5];
    const float* ln2g = (const float*)d_in[6];
    const float* ln2b = (const float*)d_in[7];
    const float* sew1 = (const float*)d_in[8];
    const float* seb1 = (const float*)d_in[9];
    const float* sew2 = (const float*)d_in[10];
    const float* seb2 = (const float*)d_in[11];

    int Nr = in_sizes[0] / CC;
    int M  = 2 * Nr;

    float* outM = (float*)d_out;
    long long osz = (long long)out_size;
    int hasIdx   = osz >= (long long)M * (CC + 4);
    int hasValid = osz >= (long long)M * (CC + 5);
    float* outIdx   = outM + (size_t)M * CC;
    float* outValid = outIdx + (hasIdx ? (size_t)M * 4 : 0);

    void *pyh = nullptr, *pyl = nullptr, *px2 = nullptr;
    cudaGetSymbolAddress(&pyh, g_Y1hi);
    cudaGetSymbolAddress(&pyl, g_Y1lo);
    cudaGetSymbolAddress(&px2, g_X2);

    cudaFuncSetAttribute(gemm1_kernel, cudaFuncAttributeMaxDynamicSharedMemorySize, SMEM_GEMM);
    cudaFuncSetAttribute(gemm2_kernel, cudaFuncAttributeMaxDynamicSharedMemorySize, SMEM_GEMM);

    if (!(hasIdx && hasValid))
        cudaMemsetAsync(d_out, 0, (size_t)out_size * sizeof(float));

    zero_kernel<<<2048, 256>>>();

    gemm1_kernel<<<296, 128, SMEM_GEMM>>>(feats, W1, ln1g, ln1b,
                                          (uint32_t*)pyh, (uint32_t*)pyl, Nr);
    gemm2_kernel<<<296, 128, SMEM_GEMM>>>((const uint32_t*)pyh, (const uint32_t*)pyl,
                                          W2, ln2g, ln2b, (float*)px2, Nr);
    se_kernel<<<1, CC>>>(sew1, seb1, sew2, seb2, 1.0f / (float)Nr);

    bitmap_kernel<<<(Nr + 255) / 256, 256>>>(indices, Nr);
    scan1_kernel<<<1024, 256>>>();
    scan2_kernel<<<1, 1024>>>();
    scan3_kernel<<<1024, 256>>>();

    zerodup_kernel<<<256, 256>>>(outM);
    scatter_kernel<<<(Nr + 7) / 8, 256>>>(feats, indices, outM, outIdx, outValid,
                                          hasIdx, hasValid, Nr);
    finalizedup_kernel<<<256, 256>>>(outM, outValid, hasValid);
    tail_kernel<<<(M + 7) / 8, 256>>>(outM, outIdx, outValid, hasIdx, hasValid, M);
}

// round 6
// speedup vs baseline: 2.6456x; 1.4769x over previous
#include <cuda_runtime.h>
#include <cuda_bf16.h>
#include <math.h>
#include <stdint.h>

#define CC 128
#define NMAX 300000
#define NWORDS (1u<<20)
#define STRIDE_Bc 4194304
#define STRIDE_Tc 262144
#define STRIDE_Hc 512

// ================= device scratch =================
__device__ float    g_X2[(size_t)NMAX*CC];
__device__ unsigned g_bitmap[NWORDS];
__device__ unsigned g_dup[NWORDS];
__device__ unsigned g_wordscan[NWORDS];
__device__ unsigned g_blocksum[1024];
__device__ unsigned g_blockoff[1024];
__device__ unsigned g_U;
__device__ unsigned g_ndup;
__device__ unsigned g_duplist[NMAX];
__device__ float    g_colsum[CC];
__device__ float    g_scale[CC];

// ================= helpers =================
__device__ __forceinline__ uint32_t smem_u32(const void* p){
    uint32_t a;
    asm("{ .reg .u64 t; cvta.to.shared.u64 t, %1; cvt.u32.u64 %0, t; }" : "=r"(a) : "l"(p));
    return a;
}

__device__ __forceinline__ void ldsm_x4(uint32_t addr, uint32_t& r0, uint32_t& r1,
                                        uint32_t& r2, uint32_t& r3){
    asm volatile("ldmatrix.sync.aligned.m8n8.x4.shared.b16 {%0,%1,%2,%3}, [%4];"
        : "=r"(r0),"=r"(r1),"=r"(r2),"=r"(r3) : "r"(addr));
}

__device__ __forceinline__ void mma_bf16(float* d, const uint32_t* a, uint32_t b0, uint32_t b1){
    asm volatile("mma.sync.aligned.m16n8k16.row.col.f32.bf16.bf16.f32 "
        "{%0,%1,%2,%3}, {%4,%5,%6,%7}, {%8,%9}, {%0,%1,%2,%3};"
        : "+f"(d[0]),"+f"(d[1]),"+f"(d[2]),"+f"(d[3])
        : "r"(a[0]),"r"(a[1]),"r"(a[2]),"r"(a[3]), "r"(b0),"r"(b1));
}

__device__ __forceinline__ void split2(float a, float b, uint32_t& hi, uint32_t& lo){
    __nv_bfloat162 h = __floats2bfloat162_rn(a, b);
    hi = *reinterpret_cast<uint32_t*>(&h);
    float ra = a - __bfloat162float(h.x);
    float rb = b - __bfloat162float(h.y);
    __nv_bfloat162 l = __floats2bfloat162_rn(ra, rb);
    lo = *reinterpret_cast<uint32_t*>(&l);
}

// ---------------- fused-kernel SMEM layout (bytes) ----------------
#define SW        136          // W panel row stride (bf16 elements)
#define AW        68           // sA row stride (uint32 words = bf16x2 pairs)
#define OFF_W1HI  0
#define OFF_W1LO  34816
#define OFF_W2HI  69632
#define OFF_W2LO  104448
#define OFF_SAHI  139264
#define OFF_SALO  174080
#define OFF_G1    208896
#define OFF_B1    209408
#define OFF_G2    209920
#define OFF_B2    210432
#define OFF_LN    210944       // float2[128][2]
#define SMEM_FUSED 212992

// one GEMM over the staged A tile: acc[8][4] covers 16 rows x 64 cols (this warp)
__device__ __forceinline__ void do_gemm(float (&acc)[8][4],
                                        const uint32_t* __restrict__ sAhi,
                                        const uint32_t* __restrict__ sAlo,
                                        uint32_t wbhi, uint32_t wblo,
                                        int arow0, int chalf, int belem, int rq, int q)
{
    #pragma unroll
    for (int ks = 0; ks < 8; ks++){
        uint32_t ah[4], al[4];
        const int wi0 = (arow0 + rq) * AW + ks*8 + q;
        const int wi1 = wi0 + 8*AW;
        ah[0] = sAhi[wi0];   ah[1] = sAhi[wi1];
        ah[2] = sAhi[wi0+4]; ah[3] = sAhi[wi1+4];
        al[0] = sAlo[wi0];   al[1] = sAlo[wi1];
        al[2] = sAlo[wi0+4]; al[3] = sAlo[wi1+4];
        #pragma unroll
        for (int np = 0; np < 4; np++){
            uint32_t boff = (uint32_t)(((chalf*64 + np*16)*SW + ks*16 + belem) * 2);
            uint32_t bh0,bh1,bh2,bh3, bl0,bl1,bl2,bl3;
            ldsm_x4(wbhi + boff, bh0,bh1,bh2,bh3);
            ldsm_x4(wblo + boff, bl0,bl1,bl2,bl3);
            mma_bf16(acc[np*2],   ah, bh0, bh1);
            mma_bf16(acc[np*2+1], ah, bh2, bh3);
            mma_bf16(acc[np*2],   ah, bl0, bl1);
            mma_bf16(acc[np*2+1], ah, bl2, bl3);
            mma_bf16(acc[np*2],   al, bh0, bh1);
            mma_bf16(acc[np*2+1], al, bh2, bh3);
        }
    }
}

// ================= fused GEMM1->LN1->ReLU->GEMM2->LN2 =================
__global__ __launch_bounds__(512, 1)
void fused_kernel(const float* __restrict__ A,
                  const float* __restrict__ W1, const float* __restrict__ g1v, const float* __restrict__ b1v,
                  const float* __restrict__ W2, const float* __restrict__ g2v, const float* __restrict__ b2v,
                  float* __restrict__ X2, int Nrows)
{
    extern __shared__ char smem[];
    uint32_t sb = smem_u32(smem);
    uint32_t* sAhi = (uint32_t*)(smem + OFF_SAHI);
    uint32_t* sAlo = (uint32_t*)(smem + OFF_SALO);
    float* sG1 = (float*)(smem + OFF_G1);
    float* sB1 = (float*)(smem + OFF_B1);
    float* sG2 = (float*)(smem + OFF_G2);
    float* sB2 = (float*)(smem + OFF_B2);
    float2* sLN = (float2*)(smem + OFF_LN);

    const int tid = threadIdx.x, lane = tid & 31, wid = tid >> 5;
    const int q = lane & 3, rq = lane >> 2;
    const int g = wid >> 1, chalf = wid & 1;
    const int jj = lane >> 3, rr = lane & 7;
    const int belem = ((jj >= 2 ? 8 : 0) + rr) * SW + ((jj & 1) ? 8 : 0);
    const int arow0 = g * 16;

    // ---- load W1/W2 hi-lo panels (each thread: one n, 32 k's) ----
    {
        int n = tid & 127, kq = tid >> 7;
        __nv_bfloat16* w1h = (__nv_bfloat16*)(smem + OFF_W1HI);
        __nv_bfloat16* w1l = (__nv_bfloat16*)(smem + OFF_W1LO);
        __nv_bfloat16* w2h = (__nv_bfloat16*)(smem + OFF_W2HI);
        __nv_bfloat16* w2l = (__nv_bfloat16*)(smem + OFF_W2LO);
        #pragma unroll 4
        for (int k = kq*32; k < kq*32 + 32; k++){
            float w = W1[k*CC + n];
            __nv_bfloat16 h = __float2bfloat16(w);
            w1h[n*SW + k] = h;
            w1l[n*SW + k] = __float2bfloat16(w - __bfloat162float(h));
            float v = W2[k*CC + n];
            __nv_bfloat16 h2 = __float2bfloat16(v);
            w2h[n*SW + k] = h2;
            w2l[n*SW + k] = __float2bfloat16(v - __bfloat162float(h2));
        }
        if (tid < CC){ sG1[tid] = g1v[tid]; sB1[tid] = b1v[tid]; sG2[tid] = g2v[tid]; sB2[tid] = b2v[tid]; }
    }
    __syncthreads();

    const uint32_t wb1h = sb + OFF_W1HI, wb1l = sb + OFF_W1LO;
    const uint32_t wb2h = sb + OFF_W2HI, wb2l = sb + OFF_W2LO;

    float csum[16];
    #pragma unroll
    for (int j = 0; j < 16; j++) csum[j] = 0.f;

    const int NT = (Nrows + 127) >> 7;
    for (int tile = blockIdx.x; tile < NT; tile += gridDim.x){
        // ---- 1. stage feats tile (128x128 f32) as bf16 hi/lo into sA ----
        {
            int row = tid >> 2, colg = tid & 3;
            int grow = tile*128 + row;
            bool ok = grow < Nrows;
            const float4* src = (const float4*)(A + (size_t)grow*CC) + colg*8;
            uint32_t* dh = sAhi + row*AW + colg*16;
            uint32_t* dl = sAlo + row*AW + colg*16;
            #pragma unroll
            for (int j = 0; j < 8; j++){
                float4 v = ok ? src[j] : make_float4(0.f,0.f,0.f,0.f);
                uint32_t h0,l0,h1,l1;
                split2(v.x, v.y, h0, l0);
                split2(v.z, v.w, h1, l1);
                dh[j*2] = h0; dh[j*2+1] = h1;
                dl[j*2] = l0; dl[j*2+1] = l1;
            }
        }
        __syncthreads();

        const int r0 = tile*128 + g*16 + rq;
        const bool ok0 = r0 < Nrows, ok1 = (r0 + 8) < Nrows;

        // ---- 2. GEMM1 ----
        float acc[8][4];
        #pragma unroll
        for (int t = 0; t < 8; t++)
            #pragma unroll
            for (int j = 0; j < 4; j++) acc[t][j] = 0.f;
        do_gemm(acc, sAhi, sAlo, wb1h, wb1l, arow0, chalf, belem, rq, q);

        // ---- 3. LN1 stats (this warp's 64 cols), cross-pair exchange ----
        float s0=0.f, q0=0.f, s1=0.f, q1=0.f;
        #pragma unroll
        for (int t = 0; t < 8; t++){
            s0 += acc[t][0] + acc[t][1];
            q0 += acc[t][0]*acc[t][0] + acc[t][1]*acc[t][1];
            s1 += acc[t][2] + acc[t][3];
            q1 += acc[t][2]*acc[t][2] + acc[t][3]*acc[t][3];
        }
        #pragma unroll
        for (int o = 1; o <= 2; o <<= 1){
            s0 += __shfl_xor_sync(0xffffffffu, s0, o);
            q0 += __shfl_xor_sync(0xffffffffu, q0, o);
            s1 += __shfl_xor_sync(0xffffffffu, s1, o);
            q1 += __shfl_xor_sync(0xffffffffu, q1, o);
        }
        if (q == 0){
            sLN[(arow0 + rq)*2 + chalf]     = make_float2(s0, q0);
            sLN[(arow0 + rq + 8)*2 + chalf] = make_float2(s1, q1);
        }
        __syncthreads();   // also guarantees all GEMM1 reads of sA are done
        {
            float2 p0 = sLN[(arow0 + rq)*2 + (chalf^1)];
            float2 p1 = sLN[(arow0 + rq + 8)*2 + (chalf^1)];
            float S0 = s0 + p0.x, Q0 = q0 + p0.y;
            float S1 = s1 + p1.x, Q1 = q1 + p1.y;
            float mu0 = S0*(1.f/128.f), mu1 = S1*(1.f/128.f);
            float rs0 = rsqrtf(Q0*(1.f/128.f) - mu0*mu0 + 1e-5f);
            float rs1 = rsqrtf(Q1*(1.f/128.f) - mu1*mu1 + 1e-5f);
            // ---- 4. LN1 apply + ReLU + split -> write Y into sA ----
            #pragma unroll
            for (int t = 0; t < 8; t++){
                int c = chalf*64 + t*8 + 2*q;
                float ga = sG1[c], gb = sG1[c+1], ba = sB1[c], bb = sB1[c+1];
                float y0 = fmaxf((acc[t][0]-mu0)*rs0*ga + ba, 0.f);
                float y1 = fmaxf((acc[t][1]-mu0)*rs0*gb + bb, 0.f);
                float y2 = fmaxf((acc[t][2]-mu1)*rs1*ga + ba, 0.f);
                float y3 = fmaxf((acc[t][3]-mu1)*rs1*gb + bb, 0.f);
                uint32_t h, l;
                int w0 = (arow0 + rq)*AW + chalf*32 + t*4 + q;
                int w1 = w0 + 8*AW;
                split2(y0, y1, h, l); sAhi[w0] = h; sAlo[w0] = l;
                split2(y2, y3, h, l); sAhi[w1] = h; sAlo[w1] = l;
            }
        }
        __syncthreads();   // Y visible to all

        // ---- 5. GEMM2 ----
        #pragma unroll
        for (int t = 0; t < 8; t++)
            #pragma unroll
            for (int j = 0; j < 4; j++) acc[t][j] = 0.f;
        do_gemm(acc, sAhi, sAlo, wb2h, wb2l, arow0, chalf, belem, rq, q);

        // ---- 6. LN2 stats + exchange ----
        s0=0.f; q0=0.f; s1=0.f; q1=0.f;
        #pragma unroll
        for (int t = 0; t < 8; t++){
            s0 += acc[t][0] + acc[t][1];
            q0 += acc[t][0]*acc[t][0] + acc[t][1]*acc[t][1];
            s1 += acc[t][2] + acc[t][3];
            q1 += acc[t][2]*acc[t][2] + acc[t][3]*acc[t][3];
        }
        #pragma unroll
        for (int o = 1; o <= 2; o <<= 1){
            s0 += __shfl_xor_sync(0xffffffffu, s0, o);
            q0 += __shfl_xor_sync(0xffffffffu, q0, o);
            s1 += __shfl_xor_sync(0xffffffffu, s1, o);
            q1 += __shfl_xor_sync(0xffffffffu, q1, o);
        }
        if (q == 0){
            sLN[(arow0 + rq)*2 + chalf]     = make_float2(s0, q0);
            sLN[(arow0 + rq + 8)*2 + chalf] = make_float2(s1, q1);
        }
        __syncthreads();   // also: all GEMM2 sA reads done -> next tile may restage
        {
            float2 p0 = sLN[(arow0 + rq)*2 + (chalf^1)];
            float2 p1 = sLN[(arow0 + rq + 8)*2 + (chalf^1)];
            float S0 = s0 + p0.x, Q0 = q0 + p0.y;
            float S1 = s1 + p1.x, Q1 = q1 + p1.y;
            float mu0 = S0*(1.f/128.f), mu1 = S1*(1.f/128.f);
            float rs0 = rsqrtf(Q0*(1.f/128.f) - mu0*mu0 + 1e-5f);
            float rs1 = rsqrtf(Q1*(1.f/128.f) - mu1*mu1 + 1e-5f);
            float* px0 = X2 + (size_t)r0*CC;
            float* px1 = px0 + 8*CC;
            #pragma unroll
            for (int t = 0; t < 8; t++){
                int c = chalf*64 + t*8 + 2*q;
                float ga = sG2[c], gb = sG2[c+1], ba = sB2[c], bb = sB2[c+1];
                if (ok0){
                    float y0 = (acc[t][0]-mu0)*rs0*ga + ba;
                    float y1 = (acc[t][1]-mu0)*rs0*gb + bb;
                    *(float2*)(px0 + c) = make_float2(y0, y1);
                    csum[t*2]   += y0;
                    csum[t*2+1] += y1;
                }
                if (ok1){
                    float y2 = (acc[t][2]-mu1)*rs1*ga + ba;
                    float y3 = (acc[t][3]-mu1)*rs1*gb + bb;
                    *(float2*)(px1 + c) = make_float2(y2, y3);
                    csum[t*2]   += y2;
                    csum[t*2+1] += y3;
                }
            }
        }
        // (next-tile restage guarded by the sync after LN2 stats above)
    }

    // ---- column-sum reduction: over rq lanes, then atomic ----
    #pragma unroll
    for (int j = 0; j < 16; j++){
        float v = csum[j];
        v += __shfl_xor_sync(0xffffffffu, v, 4);
        v += __shfl_xor_sync(0xffffffffu, v, 8);
        v += __shfl_xor_sync(0xffffffffu, v, 16);
        csum[j] = v;
    }
    if (lane < 4){
        #pragma unroll
        for (int t = 0; t < 8; t++){
            atomicAdd(&g_colsum[chalf*64 + t*8 + 2*lane],     csum[t*2]);
            atomicAdd(&g_colsum[chalf*64 + t*8 + 2*lane + 1], csum[t*2+1]);
        }
    }
}

// ================= zero per-iteration state =================
__global__ void zero_kernel() {
    unsigned i = blockIdx.x * blockDim.x + threadIdx.x;
    unsigned stride = gridDim.x * blockDim.x;
    for (unsigned w = i; w < NWORDS; w += stride){ g_bitmap[w] = 0u; g_dup[w] = 0u; }
    if (i < CC) g_colsum[i] = 0.f;
    if (i == 0) g_ndup = 0u;
}

// ================= SE gate =================
__global__ void se_kernel(const float* __restrict__ w1, const float* __restrict__ b1,
                          const float* __restrict__ w2, const float* __restrict__ b2,
                          float invN)
{
    __shared__ float sq[CC];
    __shared__ float hp[4][32];
    __shared__ float h[32];
    int t = threadIdx.x;
    sq[t] = g_colsum[t] * invN;
    __syncthreads();
    int j = t & 31, grp = t >> 5;
    float a = 0.f;
    #pragma unroll 8
    for (int c = 0; c < 32; c++){
        int cc = grp*32 + c;
        a += sq[cc] * w1[cc*32 + j];
    }
    hp[grp][j] = a;
    __syncthreads();
    if (t < 32){
        float v = b1[t] + hp[0][t] + hp[1][t] + hp[2][t] + hp[3][t];
        h[t] = fmaxf(v, 0.f);
    }
    __syncthreads();
    float o = b2[t];
    #pragma unroll
    for (int jj = 0; jj < 32; jj++) o += h[jj] * w2[jj*CC + t];
    g_scale[t] = 1.f / (1.f + expf(-o));
}

// ================= bitmap + dup detection =================
__global__ void bitmap_kernel(const int* __restrict__ idx, int Nrows) {
    int i = blockIdx.x * blockDim.x + threadIdx.x;
    if (i >= Nrows) return;
    int4 v = ((const int4*)idx)[i];
    unsigned lin = (unsigned)(v.x*STRIDE_Bc + v.y*STRIDE_Tc + v.z*STRIDE_Hc + v.w);
    unsigned bit = 1u << (lin & 31);
    unsigned old = atomicOr(&g_bitmap[lin >> 5], bit);
    if (old & bit){
        unsigned dold = atomicOr(&g_dup[lin >> 5], bit);
        if (!(dold & bit)){
            unsigned pos = atomicAdd(&g_ndup, 1u);
            if (pos < NMAX) g_duplist[pos] = lin;
        }
    }
}

__global__ void scan1_kernel() {
    int b = blockIdx.x, t = threadIdx.x;
    unsigned base = b * 1024;
    unsigned s = 0;
    #pragma unroll
    for (int j = 0; j < 4; j++) s += __popc(g_bitmap[base + t*4 + j]);
    #pragma unroll
    for (int o = 16; o > 0; o >>= 1) s += __shfl_xor_sync(0xffffffffu, s, o);
    __shared__ unsigned ws[8];
    if ((t & 31) == 0) ws[t >> 5] = s;
    __syncthreads();
    if (t == 0) {
        unsigned tot = 0;
        #pragma unroll
        for (int w = 0; w < 8; w++) tot += ws[w];
        g_blocksum[b] = tot;
    }
}

__global__ void scan2_kernel() {
    int t = threadIdx.x, lane = t & 31, w = t >> 5;
    unsigned v = g_blocksum[t];
    unsigned x = v;
    #pragma unroll
    for (int o = 1; o < 32; o <<= 1) {
        unsigned n = __shfl_up_sync(0xffffffffu, x, o);
        if (lane >= o) x += n;
    }
    __shared__ unsigned ws[32];
    if (lane == 31) ws[w] = x;
    __syncthreads();
    if (w == 0) {
        unsigned y = ws[lane];
        #pragma unroll
        for (int o = 1; o < 32; o <<= 1) {
            unsigned n = __shfl_up_sync(0xffffffffu, y, o);
            if (lane >= o) y += n;
        }
        ws[lane] = y;
    }
    __syncthreads();
    unsigned incl = x + (w ? ws[w-1] : 0u);
    g_blockoff[t] = incl - v;
    if (t == 1023) g_U = incl;
}

__global__ void scan3_kernel() {
    int b = blockIdx.x, t = threadIdx.x, lane = t & 31, w = t >> 5;
    unsigned base = b * 1024;
    unsigned wd[4];
    unsigned s = 0;
    #pragma unroll
    for (int j = 0; j < 4; j++) { wd[j] = g_bitmap[base + t*4 + j]; s += __popc(wd[j]); }
    unsigned x = s;
    #pragma unroll
    for (int o = 1; o < 32; o <<= 1) {
        unsigned n = __shfl_up_sync(0xffffffffu, x, o);
        if (lane >= o) x += n;
    }
    __shared__ unsigned ws[8];
    if (lane == 31) ws[w] = x;
    __syncthreads();
    if (t == 0) {
        unsigned acc = 0;
        #pragma unroll
        for (int i = 0; i < 8; i++) { unsigned tmp = ws[i]; ws[i] = acc; acc += tmp; }
    }
    __syncthreads();
    unsigned run = ws[w] + (x - s) + g_blockoff[b];
    #pragma unroll
    for (int j = 0; j < 4; j++) {
        g_wordscan[base + t*4 + j] = run;
        run += __popc(wd[j]);
    }
}

__device__ __forceinline__ unsigned rank_of(unsigned lin){
    unsigned wo = lin >> 5, bit = lin & 31;
    return g_wordscan[wo] + __popc(g_bitmap[wo] & ((1u << bit) - 1u));
}

// ================= zero dup rows (before scatter) =================
__global__ void zerodup_kernel(float* __restrict__ outM){
    int w = (blockIdx.x * blockDim.x + threadIdx.x) >> 5;
    int lane = threadIdx.x & 31;
    unsigned nd = g_ndup; if (nd > NMAX) nd = NMAX;
    int tot = gridDim.x * (blockDim.x >> 5);
    for (unsigned i = w; i < nd; i += tot){
        unsigned r = rank_of(g_duplist[i]);
        ((float4*)(outM + (size_t)r*CC))[lane] = make_float4(0.f,0.f,0.f,0.f);
    }
}

// ================= scatter: fused relu/valid for non-dup rows =================
__global__ void scatter_kernel(const float* __restrict__ feats, const int* __restrict__ idx,
                               float* __restrict__ outM, float* __restrict__ outIdx,
                               float* __restrict__ outValid,
                               int hasIdx, int hasValid, int Nrows)
{
    int lane = threadIdx.x & 31, w = threadIdx.x >> 5;
    int row = blockIdx.x * 8 + w;
    if (row >= Nrows) return;
    int4 iv = ((const int4*)idx)[row];
    unsigned lin = (unsigned)(iv.x*STRIDE_Bc + iv.y*STRIDE_Tc + iv.z*STRIDE_Hc + iv.w);
    unsigned wo = lin >> 5, bit = lin & 31;
    unsigned r = g_wordscan[wo] + __popc(g_bitmap[wo] & ((1u << bit) - 1u));
    bool isdup = (g_dup[wo] >> bit) & 1u;

    float4 v  = ((const float4*)g_X2)[(size_t)row*32 + lane];
    float4 f  = ((const float4*)feats)[(size_t)row*32 + lane];
    float4 sc = ((const float4*)g_scale)[lane];
    float4 o;
    o.x = v.x*sc.x + f.x;
    o.y = v.y*sc.y + f.y;
    o.z = v.z*sc.z + f.z;
    o.w = v.w*sc.w + f.w;

    if (!isdup){
        float s = fabsf(o.x) + fabsf(o.y) + fabsf(o.z) + fabsf(o.w);
        #pragma unroll
        for (int off = 16; off > 0; off >>= 1) s += __shfl_xor_sync(0xffffffffu, s, off);
        bool valid = (s > 1e-8f);
        float4 ov;
        if (valid){
            ov.x = fmaxf(o.x, 0.f); ov.y = fmaxf(o.y, 0.f);
            ov.z = fmaxf(o.z, 0.f); ov.w = fmaxf(o.w, 0.f);
        } else {
            ov = make_float4(0.f,0.f,0.f,0.f);
        }
        ((float4*)(outM + (size_t)r*CC))[lane] = ov;
        if (lane == 0 && hasValid) outValid[r] = valid ? 1.f : 0.f;
    } else {
        float* dst = &outM[(size_t)r*CC + lane*4];
        atomicAdd(dst+0, o.x); atomicAdd(dst+1, o.y);
        atomicAdd(dst+2, o.z); atomicAdd(dst+3, o.w);
    }
    if (hasIdx && lane == 0)
        ((float4*)outIdx)[r] = make_float4((float)iv.x, (float)iv.y, (float)iv.z, (float)iv.w);
}

// ================= finalize dup rows (relu + valid) =================
__global__ void finalizedup_kernel(float* __restrict__ outM, float* __restrict__ outValid,
                                   int hasValid){
    int w = (blockIdx.x * blockDim.x + threadIdx.x) >> 5;
    int lane = threadIdx.x & 31;
    unsigned nd = g_ndup; if (nd > NMAX) nd = NMAX;
    int tot = gridDim.x * (blockDim.x >> 5);
    for (unsigned i = w; i < nd; i += tot){
        unsigned r = rank_of(g_duplist[i]);
        float4* p = (float4*)(outM + (size_t)r*CC) + lane;
        float4 v = *p;
        float s = fabsf(v.x) + fabsf(v.y) + fabsf(v.z) + fabsf(v.w);
        #pragma unroll
        for (int off = 16; off > 0; off >>= 1) s += __shfl_xor_sync(0xffffffffu, s, off);
        bool valid = (s > 1e-8f);
        float4 ov;
        if (valid){
            ov.x = fmaxf(v.x, 0.f); ov.y = fmaxf(v.y, 0.f);
            ov.z = fmaxf(v.z, 0.f); ov.w = fmaxf(v.w, 0.f);
        } else {
            ov = make_float4(0.f,0.f,0.f,0.f);
        }
        *p = ov;
        if (lane == 0 && hasValid) outValid[r] = valid ? 1.f : 0.f;
    }
}

// ================= tail: rows >= U =================
__global__ void tail_kernel(float* __restrict__ outM, float* __restrict__ outIdx,
                            float* __restrict__ outValid,
                            int hasIdx, int hasValid, int Mrows)
{
    int lane = threadIdx.x & 31, w = threadIdx.x >> 5;
    int row = blockIdx.x * 8 + w;
    unsigned U = g_U;
    if (row >= Mrows || (unsigned)row < U) return;
    ((float4*)(outM + (size_t)row*CC))[lane] = make_float4(0.f,0.f,0.f,0.f);
    if (lane == 0){
        if (hasValid) outValid[row] = 0.f;
        if (hasIdx) ((float4*)outIdx)[row] = make_float4(8.f, 0.f, 0.f, 0.f);
    }
}

// ================= launch =================
extern "C" void kernel_launch(void* const* d_in, const int* in_sizes, int n_in,
                              void* d_out, int out_size)
{
    const float* feats = (const float*)d_in[0];
    const int*   indices = (const int*)d_in[1];
    const float* W1   = (const float*)d_in[2];
    const float* ln1g = (const float*)d_in[3];
    const float* ln1b = (const float*)d_in[4];
    const float* W2   = (const float*)d_in[5];
    const float* ln2g = (const float*)d_in[6];
    const float* ln2b = (const float*)d_in[7];
    const float* sew1 = (const float*)d_in[8];
    const float* seb1 = (const float*)d_in[9];
    const float* sew2 = (const float*)d_in[10];
    const float* seb2 = (const float*)d_in[11];

    int Nr = in_sizes[0] / CC;
    int M  = 2 * Nr;

    float* outM = (float*)d_out;
    long long osz = (long long)out_size;
    int hasIdx   = osz >= (long long)M * (CC + 4);
    int hasValid = osz >= (long long)M * (CC + 5);
    float* outIdx   = outM + (size_t)M * CC;
    float* outValid = outIdx + (hasIdx ? (size_t)M * 4 : 0);

    void *px2 = nullptr;
    cudaGetSymbolAddress(&px2, g_X2);

    cudaFuncSetAttribute(fused_kernel, cudaFuncAttributeMaxDynamicSharedMemorySize, SMEM_FUSED);

    if (!(hasIdx && hasValid))
        cudaMemsetAsync(d_out, 0, (size_t)out_size * sizeof(float));

    zero_kernel<<<2048, 256>>>();

    fused_kernel<<<148, 512, SMEM_FUSED>>>(feats, W1, ln1g, ln1b,
                                           W2, ln2g, ln2b, (float*)px2, Nr);
    se_kernel<<<1, CC>>>(sew1, seb1, sew2, seb2, 1.0f / (float)Nr);

    bitmap_kernel<<<(Nr + 255) / 256, 256>>>(indices, Nr);
    scan1_kernel<<<1024, 256>>>();
    scan2_kernel<<<1, 1024>>>();
    scan3_kernel<<<1024, 256>>>();

    zerodup_kernel<<<256, 256>>>(outM);
    scatter_kernel<<<(Nr + 7) / 8, 256>>>(feats, indices, outM, outIdx, outValid,
                                          hasIdx, hasValid, Nr);
    finalizedup_kernel<<<256, 256>>>(outM, outValid, hasValid);
    tail_kernel<<<(M + 7) / 8, 256>>>(outM, outIdx, outValid, hasIdx, hasValid, M);
}

// round 7
// speedup vs baseline: 2.9323x; 1.1084x over previous
#include <cuda_runtime.h>
#include <cuda_bf16.h>
#include <math.h>
#include <stdint.h>

#define CC 128
#define NMAX 300000
#define NWORDS (1u<<20)
#define STRIDE_Bc 4194304
#define STRIDE_Tc 262144
#define STRIDE_Hc 512

// ================= device scratch =================
__device__ float    g_X2[(size_t)NMAX*CC];
__device__ unsigned g_bitmap[NWORDS];
__device__ unsigned g_dup[NWORDS];
__device__ unsigned g_wordscan[NWORDS];
__device__ unsigned g_blocksum[1024];
__device__ unsigned g_blockoff[1024];
__device__ unsigned g_U;
__device__ unsigned g_ndup;
__device__ unsigned g_duplist[NMAX];
__device__ float    g_colsum[CC];
__device__ float    g_scale[CC];

// ================= helpers =================
__device__ __forceinline__ uint32_t smem_u32(const void* p){
    uint32_t a;
    asm("{ .reg .u64 t; cvta.to.shared.u64 t, %1; cvt.u32.u64 %0, t; }" : "=r"(a) : "l"(p));
    return a;
}

__device__ __forceinline__ void ldsm_x4(uint32_t addr, uint32_t& r0, uint32_t& r1,
                                        uint32_t& r2, uint32_t& r3){
    asm volatile("ldmatrix.sync.aligned.m8n8.x4.shared.b16 {%0,%1,%2,%3}, [%4];"
        : "=r"(r0),"=r"(r1),"=r"(r2),"=r"(r3) : "r"(addr));
}

__device__ __forceinline__ void mma_bf16(float* d, const uint32_t* a, uint32_t b0, uint32_t b1){
    asm volatile("mma.sync.aligned.m16n8k16.row.col.f32.bf16.bf16.f32 "
        "{%0,%1,%2,%3}, {%4,%5,%6,%7}, {%8,%9}, {%0,%1,%2,%3};"
        : "+f"(d[0]),"+f"(d[1]),"+f"(d[2]),"+f"(d[3])
        : "r"(a[0]),"r"(a[1]),"r"(a[2]),"r"(a[3]), "r"(b0),"r"(b1));
}

__device__ __forceinline__ void split2(float a, float b, uint32_t& hi, uint32_t& lo){
    __nv_bfloat162 h = __floats2bfloat162_rn(a, b);
    hi = *reinterpret_cast<uint32_t*>(&h);
    float ra = a - __bfloat162float(h.x);
    float rb = b - __bfloat162float(h.y);
    __nv_bfloat162 l = __floats2bfloat162_rn(ra, rb);
    lo = *reinterpret_cast<uint32_t*>(&l);
}

// ---------------- fused-kernel SMEM layout (bytes) ----------------
#define SW        136          // W panel row stride (bf16 elements)
#define AW        68           // sA row stride (uint32 words = bf16x2 pairs)
#define OFF_W1HI  0
#define OFF_W1LO  34816
#define OFF_W2HI  69632
#define OFF_W2LO  104448
#define OFF_SAHI  139264
#define OFF_SALO  174080
#define OFF_G1    208896
#define OFF_B1    209408
#define OFF_G2    209920
#define OFF_B2    210432
#define OFF_LN    210944       // float2[128][2]
#define SMEM_FUSED 212992

// one GEMM over the staged A tile: acc[8][4] covers 16 rows x 64 cols (this warp)
__device__ __forceinline__ void do_gemm(float (&acc)[8][4],
                                        const uint32_t* __restrict__ sAhi,
                                        const uint32_t* __restrict__ sAlo,
                                        uint32_t wbhi, uint32_t wblo,
                                        int arow0, int chalf, int belem, int rq, int q)
{
    #pragma unroll
    for (int ks = 0; ks < 8; ks++){
        uint32_t ah[4], al[4];
        const int wi0 = (arow0 + rq) * AW + ks*8 + q;
        const int wi1 = wi0 + 8*AW;
        ah[0] = sAhi[wi0];   ah[1] = sAhi[wi1];
        ah[2] = sAhi[wi0+4]; ah[3] = sAhi[wi1+4];
        al[0] = sAlo[wi0];   al[1] = sAlo[wi1];
        al[2] = sAlo[wi0+4]; al[3] = sAlo[wi1+4];
        #pragma unroll
        for (int np = 0; np < 4; np++){
            uint32_t boff = (uint32_t)(((chalf*64 + np*16)*SW + ks*16 + belem) * 2);
            uint32_t bh0,bh1,bh2,bh3, bl0,bl1,bl2,bl3;
            ldsm_x4(wbhi + boff, bh0,bh1,bh2,bh3);
            ldsm_x4(wblo + boff, bl0,bl1,bl2,bl3);
            mma_bf16(acc[np*2],   ah, bh0, bh1);
            mma_bf16(acc[np*2+1], ah, bh2, bh3);
            mma_bf16(acc[np*2],   ah, bl0, bl1);
            mma_bf16(acc[np*2+1], ah, bl2, bl3);
            mma_bf16(acc[np*2],   al, bh0, bh1);
            mma_bf16(acc[np*2+1], al, bh2, bh3);
        }
    }
}

// ================= fused GEMM1->LN1->ReLU->GEMM2->LN2 =================
__global__ __launch_bounds__(512, 1)
void fused_kernel(const float* __restrict__ A,
                  const float* __restrict__ W1, const float* __restrict__ g1v, const float* __restrict__ b1v,
                  const float* __restrict__ W2, const float* __restrict__ g2v, const float* __restrict__ b2v,
                  float* __restrict__ X2, int Nrows)
{
    extern __shared__ char smem[];
    uint32_t sb = smem_u32(smem);
    uint32_t* sAhi = (uint32_t*)(smem + OFF_SAHI);
    uint32_t* sAlo = (uint32_t*)(smem + OFF_SALO);
    float* sG1 = (float*)(smem + OFF_G1);
    float* sB1 = (float*)(smem + OFF_B1);
    float* sG2 = (float*)(smem + OFF_G2);
    float* sB2 = (float*)(smem + OFF_B2);
    float2* sLN = (float2*)(smem + OFF_LN);

    const int tid = threadIdx.x, lane = tid & 31, wid = tid >> 5;
    const int q = lane & 3, rq = lane >> 2;
    const int g = wid >> 1, chalf = wid & 1;
    const int jj = lane >> 3, rr = lane & 7;
    const int belem = ((jj >= 2 ? 8 : 0) + rr) * SW + ((jj & 1) ? 8 : 0);
    const int arow0 = g * 16;

    // ---- load W1/W2 hi-lo panels ----
    {
        int n = tid & 127, kq = tid >> 7;
        __nv_bfloat16* w1h = (__nv_bfloat16*)(smem + OFF_W1HI);
        __nv_bfloat16* w1l = (__nv_bfloat16*)(smem + OFF_W1LO);
        __nv_bfloat16* w2h = (__nv_bfloat16*)(smem + OFF_W2HI);
        __nv_bfloat16* w2l = (__nv_bfloat16*)(smem + OFF_W2LO);
        #pragma unroll 4
        for (int k = kq*32; k < kq*32 + 32; k++){
            float w = W1[k*CC + n];
            __nv_bfloat16 h = __float2bfloat16(w);
            w1h[n*SW + k] = h;
            w1l[n*SW + k] = __float2bfloat16(w - __bfloat162float(h));
            float v = W2[k*CC + n];
            __nv_bfloat16 h2 = __float2bfloat16(v);
            w2h[n*SW + k] = h2;
            w2l[n*SW + k] = __float2bfloat16(v - __bfloat162float(h2));
        }
        if (tid < CC){ sG1[tid] = g1v[tid]; sB1[tid] = b1v[tid]; sG2[tid] = g2v[tid]; sB2[tid] = b2v[tid]; }
    }
    __syncthreads();

    const uint32_t wb1h = sb + OFF_W1HI, wb1l = sb + OFF_W1LO;
    const uint32_t wb2h = sb + OFF_W2HI, wb2l = sb + OFF_W2LO;

    float csum[16];
    #pragma unroll
    for (int j = 0; j < 16; j++) csum[j] = 0.f;

    const int NT = (Nrows + 127) >> 7;
    for (int tile = blockIdx.x; tile < NT; tile += gridDim.x){
        // ---- 1. stage feats tile (128x128 f32) as bf16 hi/lo into sA ----
        {
            int row = tid >> 2, colg = tid & 3;
            int grow = tile*128 + row;
            bool ok = grow < Nrows;
            const float4* src = (const float4*)(A + (size_t)grow*CC) + colg*8;
            uint32_t* dh = sAhi + row*AW + colg*16;
            uint32_t* dl = sAlo + row*AW + colg*16;
            #pragma unroll
            for (int j = 0; j < 8; j++){
                float4 v = ok ? src[j] : make_float4(0.f,0.f,0.f,0.f);
                uint32_t h0,l0,h1,l1;
                split2(v.x, v.y, h0, l0);
                split2(v.z, v.w, h1, l1);
                dh[j*2] = h0; dh[j*2+1] = h1;
                dl[j*2] = l0; dl[j*2+1] = l1;
            }
        }
        __syncthreads();

        const int r0 = tile*128 + g*16 + rq;
        const bool ok0 = r0 < Nrows, ok1 = (r0 + 8) < Nrows;

        // ---- 2. GEMM1 ----
        float acc[8][4];
        #pragma unroll
        for (int t = 0; t < 8; t++)
            #pragma unroll
            for (int j = 0; j < 4; j++) acc[t][j] = 0.f;
        do_gemm(acc, sAhi, sAlo, wb1h, wb1l, arow0, chalf, belem, rq, q);

        // ---- 3. LN1 stats + cross-pair exchange ----
        float s0=0.f, q0=0.f, s1=0.f, q1=0.f;
        #pragma unroll
        for (int t = 0; t < 8; t++){
            s0 += acc[t][0] + acc[t][1];
            q0 += acc[t][0]*acc[t][0] + acc[t][1]*acc[t][1];
            s1 += acc[t][2] + acc[t][3];
            q1 += acc[t][2]*acc[t][2] + acc[t][3]*acc[t][3];
        }
        #pragma unroll
        for (int o = 1; o <= 2; o <<= 1){
            s0 += __shfl_xor_sync(0xffffffffu, s0, o);
            q0 += __shfl_xor_sync(0xffffffffu, q0, o);
            s1 += __shfl_xor_sync(0xffffffffu, s1, o);
            q1 += __shfl_xor_sync(0xffffffffu, q1, o);
        }
        if (q == 0){
            sLN[(arow0 + rq)*2 + chalf]     = make_float2(s0, q0);
            sLN[(arow0 + rq + 8)*2 + chalf] = make_float2(s1, q1);
        }
        __syncthreads();
        {
            float2 p0 = sLN[(arow0 + rq)*2 + (chalf^1)];
            float2 p1 = sLN[(arow0 + rq + 8)*2 + (chalf^1)];
            float S0 = s0 + p0.x, Q0 = q0 + p0.y;
            float S1 = s1 + p1.x, Q1 = q1 + p1.y;
            float mu0 = S0*(1.f/128.f), mu1 = S1*(1.f/128.f);
            float rs0 = rsqrtf(Q0*(1.f/128.f) - mu0*mu0 + 1e-5f);
            float rs1 = rsqrtf(Q1*(1.f/128.f) - mu1*mu1 + 1e-5f);
            #pragma unroll
            for (int t = 0; t < 8; t++){
                int c = chalf*64 + t*8 + 2*q;
                float ga = sG1[c], gb = sG1[c+1], ba = sB1[c], bb = sB1[c+1];
                float y0 = fmaxf((acc[t][0]-mu0)*rs0*ga + ba, 0.f);
                float y1 = fmaxf((acc[t][1]-mu0)*rs0*gb + bb, 0.f);
                float y2 = fmaxf((acc[t][2]-mu1)*rs1*ga + ba, 0.f);
                float y3 = fmaxf((acc[t][3]-mu1)*rs1*gb + bb, 0.f);
                uint32_t h, l;
                int w0 = (arow0 + rq)*AW + chalf*32 + t*4 + q;
                int w1 = w0 + 8*AW;
                split2(y0, y1, h, l); sAhi[w0] = h; sAlo[w0] = l;
                split2(y2, y3, h, l); sAhi[w1] = h; sAlo[w1] = l;
            }
        }
        __syncthreads();

        // ---- 5. GEMM2 ----
        #pragma unroll
        for (int t = 0; t < 8; t++)
            #pragma unroll
            for (int j = 0; j < 4; j++) acc[t][j] = 0.f;
        do_gemm(acc, sAhi, sAlo, wb2h, wb2l, arow0, chalf, belem, rq, q);

        // ---- 6. LN2 stats + exchange ----
        s0=0.f; q0=0.f; s1=0.f; q1=0.f;
        #pragma unroll
        for (int t = 0; t < 8; t++){
            s0 += acc[t][0] + acc[t][1];
            q0 += acc[t][0]*acc[t][0] + acc[t][1]*acc[t][1];
            s1 += acc[t][2] + acc[t][3];
            q1 += acc[t][2]*acc[t][2] + acc[t][3]*acc[t][3];
        }
        #pragma unroll
        for (int o = 1; o <= 2; o <<= 1){
            s0 += __shfl_xor_sync(0xffffffffu, s0, o);
            q0 += __shfl_xor_sync(0xffffffffu, q0, o);
            s1 += __shfl_xor_sync(0xffffffffu, s1, o);
            q1 += __shfl_xor_sync(0xffffffffu, q1, o);
        }
        if (q == 0){
            sLN[(arow0 + rq)*2 + chalf]     = make_float2(s0, q0);
            sLN[(arow0 + rq + 8)*2 + chalf] = make_float2(s1, q1);
        }
        __syncthreads();
        {
            float2 p0 = sLN[(arow0 + rq)*2 + (chalf^1)];
            float2 p1 = sLN[(arow0 + rq + 8)*2 + (chalf^1)];
            float S0 = s0 + p0.x, Q0 = q0 + p0.y;
            float S1 = s1 + p1.x, Q1 = q1 + p1.y;
            float mu0 = S0*(1.f/128.f), mu1 = S1*(1.f/128.f);
            float rs0 = rsqrtf(Q0*(1.f/128.f) - mu0*mu0 + 1e-5f);
            float rs1 = rsqrtf(Q1*(1.f/128.f) - mu1*mu1 + 1e-5f);
            float* px0 = X2 + (size_t)r0*CC;
            float* px1 = px0 + 8*CC;
            #pragma unroll
            for (int t = 0; t < 8; t++){
                int c = chalf*64 + t*8 + 2*q;
                float ga = sG2[c], gb = sG2[c+1], ba = sB2[c], bb = sB2[c+1];
                if (ok0){
                    float y0 = (acc[t][0]-mu0)*rs0*ga + ba;
                    float y1 = (acc[t][1]-mu0)*rs0*gb + bb;
                    *(float2*)(px0 + c) = make_float2(y0, y1);
                    csum[t*2]   += y0;
                    csum[t*2+1] += y1;
                }
                if (ok1){
                    float y2 = (acc[t][2]-mu1)*rs1*ga + ba;
                    float y3 = (acc[t][3]-mu1)*rs1*gb + bb;
                    *(float2*)(px1 + c) = make_float2(y2, y3);
                    csum[t*2]   += y2;
                    csum[t*2+1] += y3;
                }
            }
        }
    }

    #pragma unroll
    for (int j = 0; j < 16; j++){
        float v = csum[j];
        v += __shfl_xor_sync(0xffffffffu, v, 4);
        v += __shfl_xor_sync(0xffffffffu, v, 8);
        v += __shfl_xor_sync(0xffffffffu, v, 16);
        csum[j] = v;
    }
    if (lane < 4){
        #pragma unroll
        for (int t = 0; t < 8; t++){
            atomicAdd(&g_colsum[chalf*64 + t*8 + 2*lane],     csum[t*2]);
            atomicAdd(&g_colsum[chalf*64 + t*8 + 2*lane + 1], csum[t*2+1]);
        }
    }
}

// ================= zero per-iteration state (side stream) =================
__global__ void zero_kernel() {
    unsigned i = blockIdx.x * blockDim.x + threadIdx.x;
    unsigned stride = gridDim.x * blockDim.x;
    for (unsigned w = i; w < NWORDS; w += stride){ g_bitmap[w] = 0u; g_dup[w] = 0u; }
    if (i == 0) g_ndup = 0u;
}

// colsum zero (main stream, before fused)
__global__ void colsum0_kernel() {
    if (threadIdx.x < CC) g_colsum[threadIdx.x] = 0.f;
}

// ================= SE gate =================
__global__ void se_kernel(const float* __restrict__ w1, const float* __restrict__ b1,
                          const float* __restrict__ w2, const float* __restrict__ b2,
                          float invN)
{
    __shared__ float sq[CC];
    __shared__ float hp[4][32];
    __shared__ float h[32];
    int t = threadIdx.x;
    sq[t] = g_colsum[t] * invN;
    __syncthreads();
    int j = t & 31, grp = t >> 5;
    float a = 0.f;
    #pragma unroll 8
    for (int c = 0; c < 32; c++){
        int cc = grp*32 + c;
        a += sq[cc] * w1[cc*32 + j];
    }
    hp[grp][j] = a;
    __syncthreads();
    if (t < 32){
        float v = b1[t] + hp[0][t] + hp[1][t] + hp[2][t] + hp[3][t];
        h[t] = fmaxf(v, 0.f);
    }
    __syncthreads();
    float o = b2[t];
    #pragma unroll
    for (int jj = 0; jj < 32; jj++) o += h[jj] * w2[jj*CC + t];
    g_scale[t] = 1.f / (1.f + expf(-o));
}

// ================= bitmap + dup detection =================
__global__ void bitmap_kernel(const int* __restrict__ idx, int Nrows) {
    int i = blockIdx.x * blockDim.x + threadIdx.x;
    if (i >= Nrows) return;
    int4 v = ((const int4*)idx)[i];
    unsigned lin = (unsigned)(v.x*STRIDE_Bc + v.y*STRIDE_Tc + v.z*STRIDE_Hc + v.w);
    unsigned bit = 1u << (lin & 31);
    unsigned old = atomicOr(&g_bitmap[lin >> 5], bit);
    if (old & bit){
        unsigned dold = atomicOr(&g_dup[lin >> 5], bit);
        if (!(dold & bit)){
            unsigned pos = atomicAdd(&g_ndup, 1u);
            if (pos < NMAX) g_duplist[pos] = lin;
        }
    }
}

__global__ void scan1_kernel() {
    int b = blockIdx.x, t = threadIdx.x;
    unsigned base = b * 1024;
    unsigned s = 0;
    #pragma unroll
    for (int j = 0; j < 4; j++) s += __popc(g_bitmap[base + t*4 + j]);
    #pragma unroll
    for (int o = 16; o > 0; o >>= 1) s += __shfl_xor_sync(0xffffffffu, s, o);
    __shared__ unsigned ws[8];
    if ((t & 31) == 0) ws[t >> 5] = s;
    __syncthreads();
    if (t == 0) {
        unsigned tot = 0;
        #pragma unroll
        for (int w = 0; w < 8; w++) tot += ws[w];
        g_blocksum[b] = tot;
    }
}

__global__ void scan2_kernel() {
    int t = threadIdx.x, lane = t & 31, w = t >> 5;
    unsigned v = g_blocksum[t];
    unsigned x = v;
    #pragma unroll
    for (int o = 1; o < 32; o <<= 1) {
        unsigned n = __shfl_up_sync(0xffffffffu, x, o);
        if (lane >= o) x += n;
    }
    __shared__ unsigned ws[32];
    if (lane == 31) ws[w] = x;
    __syncthreads();
    if (w == 0) {
        unsigned y = ws[lane];
        #pragma unroll
        for (int o = 1; o < 32; o <<= 1) {
            unsigned n = __shfl_up_sync(0xffffffffu, y, o);
            if (lane >= o) y += n;
        }
        ws[lane] = y;
    }
    __syncthreads();
    unsigned incl = x + (w ? ws[w-1] : 0u);
    g_blockoff[t] = incl - v;
    if (t == 1023) g_U = incl;
}

__global__ void scan3_kernel() {
    int b = blockIdx.x, t = threadIdx.x, lane = t & 31, w = t >> 5;
    unsigned base = b * 1024;
    unsigned wd[4];
    unsigned s = 0;
    #pragma unroll
    for (int j = 0; j < 4; j++) { wd[j] = g_bitmap[base + t*4 + j]; s += __popc(wd[j]); }
    unsigned x = s;
    #pragma unroll
    for (int o = 1; o < 32; o <<= 1) {
        unsigned n = __shfl_up_sync(0xffffffffu, x, o);
        if (lane >= o) x += n;
    }
    __shared__ unsigned ws[8];
    if (lane == 31) ws[w] = x;
    __syncthreads();
    if (t == 0) {
        unsigned acc = 0;
        #pragma unroll
        for (int i = 0; i < 8; i++) { unsigned tmp = ws[i]; ws[i] = acc; acc += tmp; }
    }
    __syncthreads();
    unsigned run = ws[w] + (x - s) + g_blockoff[b];
    #pragma unroll
    for (int j = 0; j < 4; j++) {
        g_wordscan[base + t*4 + j] = run;
        run += __popc(wd[j]);
    }
}

__device__ __forceinline__ unsigned rank_of(unsigned lin){
    unsigned wo = lin >> 5, bit = lin & 31;
    return g_wordscan[wo] + __popc(g_bitmap[wo] & ((1u << bit) - 1u));
}

// ================= zero dup rows (side stream, after scans) =================
__global__ void zerodup_kernel(float* __restrict__ outM){
    int w = (blockIdx.x * blockDim.x + threadIdx.x) >> 5;
    int lane = threadIdx.x & 31;
    unsigned nd = g_ndup; if (nd > NMAX) nd = NMAX;
    int tot = gridDim.x * (blockDim.x >> 5);
    for (unsigned i = w; i < nd; i += tot){
        unsigned r = rank_of(g_duplist[i]);
        ((float4*)(outM + (size_t)r*CC))[lane] = make_float4(0.f,0.f,0.f,0.f);
    }
}

// ================= tail: rows >= U (side stream) =================
__global__ void tail_kernel(float* __restrict__ outM, float* __restrict__ outIdx,
                            float* __restrict__ outValid,
                            int hasIdx, int hasValid, int Mrows)
{
    int lane = threadIdx.x & 31, w = threadIdx.x >> 5;
    int row = blockIdx.x * 8 + w;
    unsigned U = g_U;
    if (row >= Mrows || (unsigned)row < U) return;
    ((float4*)(outM + (size_t)row*CC))[lane] = make_float4(0.f,0.f,0.f,0.f);
    if (lane == 0){
        if (hasValid) outValid[row] = 0.f;
        if (hasIdx) ((float4*)outIdx)[row] = make_float4(8.f, 0.f, 0.f, 0.f);
    }
}

// ================= scatter: fused relu/valid for non-dup rows =================
__global__ void scatter_kernel(const float* __restrict__ feats, const int* __restrict__ idx,
                               float* __restrict__ outM, float* __restrict__ outIdx,
                               float* __restrict__ outValid,
                               int hasIdx, int hasValid, int Nrows)
{
    int lane = threadIdx.x & 31, w = threadIdx.x >> 5;
    int row = blockIdx.x * 8 + w;
    if (row >= Nrows) return;
    int4 iv = ((const int4*)idx)[row];
    unsigned lin = (unsigned)(iv.x*STRIDE_Bc + iv.y*STRIDE_Tc + iv.z*STRIDE_Hc + iv.w);
    unsigned wo = lin >> 5, bit = lin & 31;
    unsigned r = g_wordscan[wo] + __popc(g_bitmap[wo] & ((1u << bit) - 1u));
    bool isdup = (g_dup[wo] >> bit) & 1u;

    float4 v  = ((const float4*)g_X2)[(size_t)row*32 + lane];
    float4 f  = ((const float4*)feats)[(size_t)row*32 + lane];
    float4 sc = ((const float4*)g_scale)[lane];
    float4 o;
    o.x = v.x*sc.x + f.x;
    o.y = v.y*sc.y + f.y;
    o.z = v.z*sc.z + f.z;
    o.w = v.w*sc.w + f.w;

    if (!isdup){
        float s = fabsf(o.x) + fabsf(o.y) + fabsf(o.z) + fabsf(o.w);
        #pragma unroll
        for (int off = 16; off > 0; off >>= 1) s += __shfl_xor_sync(0xffffffffu, s, off);
        bool valid = (s > 1e-8f);
        float4 ov;
        if (valid){
            ov.x = fmaxf(o.x, 0.f); ov.y = fmaxf(o.y, 0.f);
            ov.z = fmaxf(o.z, 0.f); ov.w = fmaxf(o.w, 0.f);
        } else {
            ov = make_float4(0.f,0.f,0.f,0.f);
        }
        ((float4*)(outM + (size_t)r*CC))[lane] = ov;
        if (lane == 0 && hasValid) outValid[r] = valid ? 1.f : 0.f;
    } else {
        float* dst = &outM[(size_t)r*CC + lane*4];
        atomicAdd(dst+0, o.x); atomicAdd(dst+1, o.y);
        atomicAdd(dst+2, o.z); atomicAdd(dst+3, o.w);
    }
    if (hasIdx && lane == 0)
        ((float4*)outIdx)[r] = make_float4((float)iv.x, (float)iv.y, (float)iv.z, (float)iv.w);
}

// ================= finalize dup rows (relu + valid) =================
__global__ void finalizedup_kernel(float* __restrict__ outM, float* __restrict__ outValid,
                                   int hasValid){
    int w = (blockIdx.x * blockDim.x + threadIdx.x) >> 5;
    int lane = threadIdx.x & 31;
    unsigned nd = g_ndup; if (nd > NMAX) nd = NMAX;
    int tot = gridDim.x * (blockDim.x >> 5);
    for (unsigned i = w; i < nd; i += tot){
        unsigned r = rank_of(g_duplist[i]);
        float4* p = (float4*)(outM + (size_t)r*CC) + lane;
        float4 v = *p;
        float s = fabsf(v.x) + fabsf(v.y) + fabsf(v.z) + fabsf(v.w);
        #pragma unroll
        for (int off = 16; off > 0; off >>= 1) s += __shfl_xor_sync(0xffffffffu, s, off);
        bool valid = (s > 1e-8f);
        float4 ov;
        if (valid){
            ov.x = fmaxf(v.x, 0.f); ov.y = fmaxf(v.y, 0.f);
            ov.z = fmaxf(v.z, 0.f); ov.w = fmaxf(v.w, 0.f);
        } else {
            ov = make_float4(0.f,0.f,0.f,0.f);
        }
        *p = ov;
        if (lane == 0 && hasValid) outValid[r] = valid ? 1.f : 0.f;
    }
}

// ================= launch =================
extern "C" void kernel_launch(void* const* d_in, const int* in_sizes, int n_in,
                              void* d_out, int out_size)
{
    const float* feats = (const float*)d_in[0];
    const int*   indices = (const int*)d_in[1];
    const float* W1   = (const float*)d_in[2];
    const float* ln1g = (const float*)d_in[3];
    const float* ln1b = (const float*)d_in[4];
    const float* W2   = (const float*)d_in[5];
    const float* ln2g = (const float*)d_in[6];
    const float* ln2b = (const float*)d_in[7];
    const float* sew1 = (const float*)d_in[8];
    const float* seb1 = (const float*)d_in[9];
    const float* sew2 = (const float*)d_in[10];
    const float* seb2 = (const float*)d_in[11];

    int Nr = in_sizes[0] / CC;
    int M  = 2 * Nr;

    float* outM = (float*)d_out;
    long long osz = (long long)out_size;
    int hasIdx   = osz >= (long long)M * (CC + 4);
    int hasValid = osz >= (long long)M * (CC + 5);
    float* outIdx   = outM + (size_t)M * CC;
    float* outValid = outIdx + (hasIdx ? (size_t)M * 4 : 0);

    void *px2 = nullptr;
    cudaGetSymbolAddress(&px2, g_X2);

    cudaFuncSetAttribute(fused_kernel, cudaFuncAttributeMaxDynamicSharedMemorySize, SMEM_FUSED);

    if (!(hasIdx && hasValid))
        cudaMemsetAsync(d_out, 0, (size_t)out_size * sizeof(float));

    // ---- fork side stream for the index pipeline (runs under the GEMM) ----
    cudaStream_t s2;
    cudaStreamCreateWithFlags(&s2, cudaStreamNonBlocking);
    cudaEvent_t evFork, evJoin;
    cudaEventCreateWithFlags(&evFork, cudaEventDisableTiming);
    cudaEventCreateWithFlags(&evJoin, cudaEventDisableTiming);

    cudaEventRecord(evFork, 0);
    cudaStreamWaitEvent(s2, evFork, 0);

    // side stream: bitmap state -> bitmap -> scans -> zerodup -> tail
    zero_kernel<<<2048, 256, 0, s2>>>();
    bitmap_kernel<<<(Nr + 255) / 256, 256, 0, s2>>>(indices, Nr);
    scan1_kernel<<<1024, 256, 0, s2>>>();
    scan2_kernel<<<1, 1024, 0, s2>>>();
    scan3_kernel<<<1024, 256, 0, s2>>>();
    zerodup_kernel<<<256, 256, 0, s2>>>(outM);
    tail_kernel<<<(M + 7) / 8, 256, 0, s2>>>(outM, outIdx, outValid, hasIdx, hasValid, M);
    cudaEventRecord(evJoin, s2);

    // main stream: GEMM pipeline
    colsum0_kernel<<<1, 128>>>();
    fused_kernel<<<148, 512, SMEM_FUSED>>>(feats, W1, ln1g, ln1b,
                                           W2, ln2g, ln2b, (float*)px2, Nr);
    se_kernel<<<1, CC>>>(sew1, seb1, sew2, seb2, 1.0f / (float)Nr);

    // join, then scatter + dup finalize
    cudaStreamWaitEvent(0, evJoin, 0);
    scatter_kernel<<<(Nr + 7) / 8, 256>>>(feats, indices, outM, outIdx, outValid,
                                          hasIdx, hasValid, Nr);
    finalizedup_kernel<<<256, 256>>>(outM, outValid, hasValid);
    // NOTE: stream/events intentionally not destroyed here — destroying a
    // forked stream mid-capture invalidates the graph; leaked handles are
    // bounded (kernel_launch is called O(1) times).
}